// round 1
// baseline (speedup 1.0000x reference)
#include <cuda_runtime.h>
#include <math.h>

#define BB 16
#define TLEN 2048
#define HH 512
#define BT (BB*TLEN)
#define KTOT (3*HH)

// scratch (static device memory; no allocations)
__device__ float g_W[KTOT*HH];      // [k_lin][o], k_lin = shift*512 + i
__device__ float g_partial[BT*4];   // per-t partial logits from 4 o-groups
__device__ float g_alpha[BT];
__device__ float g_cur[BT];
__device__ float g_remv[BT];
__device__ int   g_fire[BT];
__device__ int   g_nf[BB];

// ---------------- weight re-layout: conv_w[o][i][s] -> g_W[(s*512+i)*512 + o]
__global__ void k_wprep(const float* __restrict__ cw) {
    int idx = blockIdx.x*256 + threadIdx.x;
    if (idx >= KTOT*HH) return;
    int o    = idx & (HH-1);
    int klin = idx >> 9;
    int i    = klin & (HH-1);
    int s    = klin >> 9;
    g_W[idx] = cw[(o*HH + i)*3 + s];
}

// ---------------- fused conv-GEMM + relu + out_w reduction ----------------
// Block tile: 128 t x 128 o, K = 1536 (3 shifts x 512 channels), fp32.
#define TM 128
#define TN 128
#define TKc 32
#define APAD 36

__global__ __launch_bounds__(256,2)
void k_gemm(const float* __restrict__ hidden,
            const float* __restrict__ convb,
            const float* __restrict__ outw) {
    __shared__ float As[TM][APAD];   // [t][k]
    __shared__ float Bs[TKc][TN];    // [k][o]

    int tid = threadIdx.x;
    int tx = tid & 15, ty = tid >> 4;
    int b  = blockIdx.x >> 4;
    int t0 = (blockIdx.x & 15) * TM;
    int o0 = blockIdx.y * TN;
    const float* hb = hidden + (size_t)b*TLEN*HH;

    float acc[8][8];
    #pragma unroll
    for (int r=0;r<8;r++)
        #pragma unroll
        for (int c=0;c<8;c++) acc[r][c] = 0.f;

    int lr = tid >> 3;            // A: row 0..31
    int lc = (tid & 7) << 2;      // A: col 0..28
    int brr = tid >> 5;           // B: row 0..7
    int bcc = (tid & 31) << 2;    // B: col 0..124

    for (int kc = 0; kc < KTOT/TKc; ++kc) {
        int k0 = kc*TKc;
        int sh = k0 >> 9;         // shift 0..2 (constant within 32-chunk)
        int i0 = k0 & 511;
        #pragma unroll
        for (int it=0; it<4; ++it) {
            int rr = lr + it*32;
            int gt = t0 + rr + sh - 1;          // per-batch zero padding
            float4 v = make_float4(0.f,0.f,0.f,0.f);
            if (gt >= 0 && gt < TLEN)
                v = *(const float4*)(hb + (size_t)gt*HH + i0 + lc);
            *(float4*)&As[rr][lc] = v;
        }
        #pragma unroll
        for (int it=0; it<4; ++it) {
            int kk = brr + it*8;
            *(float4*)&Bs[kk][bcc] = *(const float4*)(g_W + (size_t)(k0+kk)*HH + o0 + bcc);
        }
        __syncthreads();

        #pragma unroll 16
        for (int k=0;k<TKc;k++) {
            float a0[4], a1[4];
            #pragma unroll
            for (int r=0;r<4;r++) { a0[r]=As[ty*4+r][k]; a1[r]=As[64+ty*4+r][k]; }
            float4 b0 = *(float4*)&Bs[k][tx*4];
            float4 b1 = *(float4*)&Bs[k][64+tx*4];
            float bv[8] = {b0.x,b0.y,b0.z,b0.w,b1.x,b1.y,b1.z,b1.w};
            #pragma unroll
            for (int r=0;r<4;r++)
                #pragma unroll
                for (int c=0;c<8;c++) {
                    acc[r][c]   = fmaf(a0[r], bv[c], acc[r][c]);
                    acc[r+4][c] = fmaf(a1[r], bv[c], acc[r+4][c]);
                }
        }
        __syncthreads();
    }

    // epilogue: y = acc + conv_b + residual; relu; dot with out_w over this o-tile
    float4 cb0 = *(const float4*)(convb + o0 + tx*4);
    float4 cb1 = *(const float4*)(convb + o0 + 64 + tx*4);
    float4 w0  = *(const float4*)(outw  + o0 + tx*4);
    float4 w1  = *(const float4*)(outw  + o0 + 64 + tx*4);
    float cbv[8] = {cb0.x,cb0.y,cb0.z,cb0.w,cb1.x,cb1.y,cb1.z,cb1.w};
    float wv[8]  = {w0.x,w0.y,w0.z,w0.w,w1.x,w1.y,w1.z,w1.w};

    float red[8];
    #pragma unroll
    for (int r=0;r<8;r++) {
        int tt = (r<4) ? (ty*4+r) : (64+ty*4+(r-4));
        int gt = t0 + tt;
        float4 h0 = *(const float4*)(hb + (size_t)gt*HH + o0 + tx*4);
        float4 h1 = *(const float4*)(hb + (size_t)gt*HH + o0 + 64 + tx*4);
        float hv[8] = {h0.x,h0.y,h0.z,h0.w,h1.x,h1.y,h1.z,h1.w};
        float s = 0.f;
        #pragma unroll
        for (int c=0;c<8;c++) {
            float y = acc[r][c] + cbv[c] + hv[c];
            y = fmaxf(y, 0.f);
            s = fmaf(y, wv[c], s);
        }
        red[r] = s;
    }

    __syncthreads();
    float* sred = &As[0][0];
    #pragma unroll
    for (int r=0;r<8;r++) {
        int tt = (r<4) ? (ty*4+r) : (64+ty*4+(r-4));
        sred[tt*16 + tx] = red[r];
    }
    __syncthreads();
    if (tid < 128) {
        float s = 0.f;
        #pragma unroll
        for (int x=0;x<16;x++) s += sred[tid*16 + x];
        g_partial[(size_t)(b*TLEN + t0 + tid)*4 + blockIdx.y] = s;
    }
}

// ---------------- combine partials -> sigmoid -> alpha ----------------
__global__ void k_alpha(const float* __restrict__ mask, const float* __restrict__ outb) {
    int i = blockIdx.x*256 + threadIdx.x;
    if (i >= BT) return;
    float l = ((g_partial[i*4+0] + g_partial[i*4+1]) +
               (g_partial[i*4+2] + g_partial[i*4+3])) + outb[0];
    float a = 1.f / (1.f + expf(-l));
    a = fmaxf(a * 1.0f - 0.0f, 0.f);   // SMOOTH=1, NOISE=0
    a *= mask[i];                       // mask is [B,1,T] -> flat b*T+t
    g_alpha[i] = a;
}

// ---------------- sequential CIF scan (bit-exact replica of reference fp32) ---
__global__ void k_scan() {
    int b = threadIdx.x;
    if (b >= BB) return;
    const float* al = g_alpha + b*TLEN;
    float integ = 0.f;
    int j = 0;
    for (int t=0; t<TLEN; ++t) {
        float alpha = al[t];
        float dist  = 1.0f - integ;
        integ = integ + alpha;
        bool fire = (integ >= 1.0f);
        float cur = fire ? dist : alpha;
        g_cur[b*TLEN + t] = cur;
        if (fire) {
            g_fire[b*TLEN + j] = t;
            g_remv[b*TLEN + j] = alpha - cur;
            j++;
            integ -= 1.0f;
        }
    }
    g_nf[b] = j;
}

// ---------------- parallel output gather: acoustic[b,j] = segment sum --------
__global__ void k_out(const float* __restrict__ hidden, float* __restrict__ out) {
    int j = blockIdx.x;
    int b = blockIdx.y;
    int c = threadIdx.x << 2;   // 128 threads x float4 = 512
    const float* hb = hidden + (size_t)b*TLEN*HH;
    float4 acc = make_float4(0.f,0.f,0.f,0.f);
    if (j < g_nf[b]) {
        int tend = g_fire[b*TLEN + j];
        int ts = 0;
        if (j > 0) {
            int tp = g_fire[b*TLEN + j - 1];
            float rv = g_remv[b*TLEN + j - 1];
            float4 h = *(const float4*)(hb + (size_t)tp*HH + c);
            acc.x = rv*h.x; acc.y = rv*h.y; acc.z = rv*h.z; acc.w = rv*h.w;
            ts = tp + 1;
        }
        for (int t = ts; t <= tend; ++t) {
            float w = g_cur[b*TLEN + t];
            float4 h = *(const float4*)(hb + (size_t)t*HH + c);
            acc.x = fmaf(w, h.x, acc.x);
            acc.y = fmaf(w, h.y, acc.y);
            acc.z = fmaf(w, h.z, acc.z);
            acc.w = fmaf(w, h.w, acc.w);
        }
    }
    *(float4*)(out + (size_t)(b*TLEN + j)*HH + c) = acc;
}

extern "C" void kernel_launch(void* const* d_in, const int* in_sizes, int n_in,
                              void* d_out, int out_size) {
    const float* hidden = (const float*)d_in[0];
    const float* mask   = (const float*)d_in[1];
    const float* conv_w = (const float*)d_in[2];
    const float* conv_b = (const float*)d_in[3];
    const float* out_w  = (const float*)d_in[4];
    const float* out_b  = (const float*)d_in[5];
    float* out = (float*)d_out;

    k_wprep<<<(KTOT*HH + 255)/256, 256>>>(conv_w);
    dim3 gg(256, 4);
    k_gemm<<<gg, 256>>>(hidden, conv_b, out_w);
    k_alpha<<<BT/256, 256>>>(mask, out_b);
    k_scan<<<1, 16>>>();
    dim3 go(TLEN, BB);
    k_out<<<go, 128>>>(hidden, out);
}

// round 2
// speedup vs baseline: 1.0080x; 1.0080x over previous
#include <cuda_runtime.h>
#include <math.h>

#define BB 16
#define TLEN 2048
#define HH 512
#define BT (BB*TLEN)
#define KTOT (3*HH)

// scratch (static device memory; no allocations)
__device__ float g_W[KTOT*HH];      // [k_lin][o], k_lin = shift*512 + i
__device__ float g_partial[BT*4];   // per-t partial logits from 4 o-groups
__device__ float g_alpha[BT];
__device__ float g_cur[BT];
__device__ float g_remv[BT];
__device__ int   g_fire[BT];
__device__ int   g_nf[BB];

// ---------------- packed f32x2 helpers (sm_100+) ----------------
__device__ __forceinline__ unsigned long long pack2(float a) {
    unsigned long long r;
    unsigned int u = __float_as_uint(a);
    asm("mov.b64 %0, {%1, %2};" : "=l"(r) : "r"(u), "r"(u));
    return r;
}
__device__ __forceinline__ void fma2(unsigned long long& d,
                                     unsigned long long a,
                                     unsigned long long b) {
    asm("fma.rn.f32x2 %0, %1, %2, %0;" : "+l"(d) : "l"(a), "l"(b));
}
__device__ __forceinline__ float lo32(unsigned long long v) {
    return __uint_as_float((unsigned int)v);
}
__device__ __forceinline__ float hi32(unsigned long long v) {
    return __uint_as_float((unsigned int)(v >> 32));
}

// ---------------- weight re-layout: conv_w[o][i][s] -> g_W[(s*512+i)*512 + o]
__global__ void k_wprep(const float* __restrict__ cw) {
    int idx = blockIdx.x*256 + threadIdx.x;
    if (idx >= KTOT*HH) return;
    int o    = idx & (HH-1);
    int klin = idx >> 9;
    int i    = klin & (HH-1);
    int s    = klin >> 9;
    g_W[idx] = cw[(o*HH + i)*3 + s];
}

// ---------------- fused conv-GEMM + relu + out_w reduction ----------------
// Block tile: 128 t x 128 o, K = 1536 (3 shifts x 512 channels), fp32.
#define TM 128
#define TN 128
#define TKc 32
#define APAD 36

__global__ __launch_bounds__(256,2)
void k_gemm(const float* __restrict__ hidden,
            const float* __restrict__ convb,
            const float* __restrict__ outw) {
    __shared__ float As[TM][APAD];   // [t][k]
    __shared__ float Bs[TKc][TN];    // [k][o]

    int tid = threadIdx.x;
    int tx = tid & 15, ty = tid >> 4;
    int b  = blockIdx.x >> 4;
    int t0 = (blockIdx.x & 15) * TM;
    int o0 = blockIdx.y * TN;
    const float* hb = hidden + (size_t)b*TLEN*HH;

    // acc2[r][c] holds fp32 pair for columns (2c, 2c+1) of the 8-col group
    unsigned long long acc2[8][4];
    #pragma unroll
    for (int r=0;r<8;r++)
        #pragma unroll
        for (int c=0;c<4;c++) acc2[r][c] = 0ull;

    int lr = tid >> 3;            // A: row 0..31
    int lc = (tid & 7) << 2;      // A: col 0..28
    int brr = tid >> 5;           // B: row 0..7
    int bcc = (tid & 31) << 2;    // B: col 0..124

    for (int kc = 0; kc < KTOT/TKc; ++kc) {
        int k0 = kc*TKc;
        int sh = k0 >> 9;         // shift 0..2 (constant within 32-chunk)
        int i0 = k0 & 511;
        #pragma unroll
        for (int it=0; it<4; ++it) {
            int rr = lr + it*32;
            int gt = t0 + rr + sh - 1;          // per-batch zero padding
            float4 v = make_float4(0.f,0.f,0.f,0.f);
            if (gt >= 0 && gt < TLEN)
                v = *(const float4*)(hb + (size_t)gt*HH + i0 + lc);
            *(float4*)&As[rr][lc] = v;
        }
        #pragma unroll
        for (int it=0; it<4; ++it) {
            int kk = brr + it*8;
            *(float4*)&Bs[kk][bcc] = *(const float4*)(g_W + (size_t)(k0+kk)*HH + o0 + bcc);
        }
        __syncthreads();

        #pragma unroll 16
        for (int k=0;k<TKc;k++) {
            ulonglong2 bA = *(const ulonglong2*)&Bs[k][tx*4];
            ulonglong2 bB = *(const ulonglong2*)&Bs[k][64+tx*4];
            unsigned long long bp0 = bA.x, bp1 = bA.y, bp2 = bB.x, bp3 = bB.y;
            #pragma unroll
            for (int r=0;r<4;r++) {
                unsigned long long pa0 = pack2(As[ty*4+r][k]);
                unsigned long long pa1 = pack2(As[64+ty*4+r][k]);
                fma2(acc2[r][0],   pa0, bp0);
                fma2(acc2[r][1],   pa0, bp1);
                fma2(acc2[r][2],   pa0, bp2);
                fma2(acc2[r][3],   pa0, bp3);
                fma2(acc2[r+4][0], pa1, bp0);
                fma2(acc2[r+4][1], pa1, bp1);
                fma2(acc2[r+4][2], pa1, bp2);
                fma2(acc2[r+4][3], pa1, bp3);
            }
        }
        __syncthreads();
    }

    // unpack acc2 -> acc[r][0..7]; col mapping: 0..3 -> tx*4+c, 4..7 -> 64+tx*4+(c-4)
    float acc[8][8];
    #pragma unroll
    for (int r=0;r<8;r++) {
        #pragma unroll
        for (int c=0;c<4;c++) {
            acc[r][2*c]   = lo32(acc2[r][c]);
            acc[r][2*c+1] = hi32(acc2[r][c]);
        }
    }
    // reorder: acc pairs are (tx*4,tx*4+1),(tx*4+2,tx*4+3),(64+tx*4,64+tx*4+1),(64+tx*4+2,+3)
    // which matches the original [c]=0..3 -> tx*4+c (c0,c1 from pair0/1), 4..7 -> 64+tx*4 (pair2/3). OK.

    // epilogue: y = acc + conv_b + residual; relu; dot with out_w over this o-tile
    float4 cb0 = *(const float4*)(convb + o0 + tx*4);
    float4 cb1 = *(const float4*)(convb + o0 + 64 + tx*4);
    float4 w0  = *(const float4*)(outw  + o0 + tx*4);
    float4 w1  = *(const float4*)(outw  + o0 + 64 + tx*4);
    float cbv[8] = {cb0.x,cb0.y,cb0.z,cb0.w,cb1.x,cb1.y,cb1.z,cb1.w};
    float wv[8]  = {w0.x,w0.y,w0.z,w0.w,w1.x,w1.y,w1.z,w1.w};

    float red[8];
    #pragma unroll
    for (int r=0;r<8;r++) {
        int tt = (r<4) ? (ty*4+r) : (64+ty*4+(r-4));
        int gt = t0 + tt;
        float4 h0 = *(const float4*)(hb + (size_t)gt*HH + o0 + tx*4);
        float4 h1 = *(const float4*)(hb + (size_t)gt*HH + o0 + 64 + tx*4);
        float hv[8] = {h0.x,h0.y,h0.z,h0.w,h1.x,h1.y,h1.z,h1.w};
        float s = 0.f;
        #pragma unroll
        for (int c=0;c<8;c++) {
            float y = acc[r][c] + cbv[c] + hv[c];
            y = fmaxf(y, 0.f);
            s = fmaf(y, wv[c], s);
        }
        red[r] = s;
    }

    __syncthreads();
    float* sred = &As[0][0];
    #pragma unroll
    for (int r=0;r<8;r++) {
        int tt = (r<4) ? (ty*4+r) : (64+ty*4+(r-4));
        sred[tt*16 + tx] = red[r];
    }
    __syncthreads();
    if (tid < 128) {
        float s = 0.f;
        #pragma unroll
        for (int x=0;x<16;x++) s += sred[tid*16 + x];
        g_partial[(size_t)(b*TLEN + t0 + tid)*4 + blockIdx.y] = s;
    }
}

// ---------------- combine partials -> sigmoid -> alpha ----------------
__global__ void k_alpha(const float* __restrict__ mask, const float* __restrict__ outb) {
    int i = blockIdx.x*256 + threadIdx.x;
    if (i >= BT) return;
    float l = ((g_partial[i*4+0] + g_partial[i*4+1]) +
               (g_partial[i*4+2] + g_partial[i*4+3])) + outb[0];
    float a = 1.f / (1.f + expf(-l));
    a = fmaxf(a * 1.0f - 0.0f, 0.f);   // SMOOTH=1, NOISE=0
    a *= mask[i];                       // mask is [B,1,T] -> flat b*T+t
    g_alpha[i] = a;
}

// ---------------- sequential CIF scan (exact fp32 replica, software-pipelined)
__global__ void k_scan() {
    int b = blockIdx.x;
    if (threadIdx.x != 0) return;
    const float4* al4 = (const float4*)(g_alpha + b*TLEN);
    float4* cur4 = (float4*)(g_cur + b*TLEN);
    int base = b*TLEN;
    float integ = 0.f;
    int j = 0;
    float4 c0 = al4[0], c1 = al4[1];
    #pragma unroll 1
    for (int ch = 0; ch < TLEN/8; ++ch) {
        float4 n0 = make_float4(0,0,0,0), n1 = make_float4(0,0,0,0);
        if (ch + 1 < TLEN/8) { n0 = al4[(ch+1)*2]; n1 = al4[(ch+1)*2 + 1]; }
        float av[8] = {c0.x,c0.y,c0.z,c0.w,c1.x,c1.y,c1.z,c1.w};
        float cv[8];
        int t0 = ch*8;
        #pragma unroll
        for (int s=0;s<8;s++) {
            float alpha = av[s];
            float dist  = 1.0f - integ;
            integ = integ + alpha;
            bool fire = (integ >= 1.0f);
            float cur = fire ? dist : alpha;
            cv[s] = cur;
            if (fire) {
                g_fire[base + j] = t0 + s;
                g_remv[base + j] = alpha - cur;
                j++;
                integ -= 1.0f;
            }
        }
        cur4[ch*2]   = make_float4(cv[0],cv[1],cv[2],cv[3]);
        cur4[ch*2+1] = make_float4(cv[4],cv[5],cv[6],cv[7]);
        c0 = n0; c1 = n1;
    }
    g_nf[b] = j;
}

// ---------------- parallel output gather: acoustic[b,j] = segment sum --------
__global__ void k_out(const float* __restrict__ hidden, float* __restrict__ out) {
    int j = blockIdx.x;
    int b = blockIdx.y;
    int c = threadIdx.x << 2;   // 128 threads x float4 = 512
    const float* hb = hidden + (size_t)b*TLEN*HH;
    float4 acc = make_float4(0.f,0.f,0.f,0.f);
    if (j < g_nf[b]) {
        int tend = g_fire[b*TLEN + j];
        int ts = 0;
        if (j > 0) {
            int tp = g_fire[b*TLEN + j - 1];
            float rv = g_remv[b*TLEN + j - 1];
            float4 h = *(const float4*)(hb + (size_t)tp*HH + c);
            acc.x = rv*h.x; acc.y = rv*h.y; acc.z = rv*h.z; acc.w = rv*h.w;
            ts = tp + 1;
        }
        for (int t = ts; t <= tend; ++t) {
            float w = g_cur[b*TLEN + t];
            float4 h = *(const float4*)(hb + (size_t)t*HH + c);
            acc.x = fmaf(w, h.x, acc.x);
            acc.y = fmaf(w, h.y, acc.y);
            acc.z = fmaf(w, h.z, acc.z);
            acc.w = fmaf(w, h.w, acc.w);
        }
    }
    *(float4*)(out + (size_t)(b*TLEN + j)*HH + c) = acc;
}

extern "C" void kernel_launch(void* const* d_in, const int* in_sizes, int n_in,
                              void* d_out, int out_size) {
    const float* hidden = (const float*)d_in[0];
    const float* mask   = (const float*)d_in[1];
    const float* conv_w = (const float*)d_in[2];
    const float* conv_b = (const float*)d_in[3];
    const float* out_w  = (const float*)d_in[4];
    const float* out_b  = (const float*)d_in[5];
    float* out = (float*)d_out;

    k_wprep<<<(KTOT*HH + 255)/256, 256>>>(conv_w);
    dim3 gg(256, 4);
    k_gemm<<<gg, 256>>>(hidden, conv_b, out_w);
    k_alpha<<<BT/256, 256>>>(mask, out_b);
    k_scan<<<16, 32>>>();
    dim3 go(TLEN, BB);
    k_out<<<go, 128>>>(hidden, out);
}

// round 3
// speedup vs baseline: 1.6296x; 1.6166x over previous
#include <cuda_runtime.h>
#include <cuda_bf16.h>
#include <math.h>
#include <stdint.h>

#define BB 16
#define TLEN 2048
#define HH 512
#define BT (BB*TLEN)
#define KTOT 1536
#define TK 16
#define NKC (KTOT/TK)     // 96
#define ROWPAD 24         // 16 data + 8 pad bf16 per row (48B stride)

// static device scratch (no allocations)
__device__ __nv_bfloat16 g_Ahi[(size_t)BT*HH];
__device__ __nv_bfloat16 g_Alo[(size_t)BT*HH];
__device__ __nv_bfloat16 g_Whi[HH*KTOT];   // [o][klin], klin = s*512+i
__device__ __nv_bfloat16 g_Wlo[HH*KTOT];
__device__ float g_partial[BT*4];
__device__ float g_alpha[BT];
__device__ float g_cur[BT];
__device__ float g_remv[BT];
__device__ int   g_fire[BT];
__device__ int   g_nf[BB];

__device__ __forceinline__ uint32_t smem_u32(const void* p) {
    uint32_t r;
    asm("{ .reg .u64 t; cvta.to.shared.u64 t, %1; cvt.u32.u64 %0, t; }"
        : "=r"(r) : "l"(p));
    return r;
}
__device__ __forceinline__ void cp16(uint32_t dst, const void* src, int pb) {
    asm volatile("cp.async.cg.shared.global [%0], [%1], 16, %2;"
                 :: "r"(dst), "l"(src), "r"(pb));
}
__device__ __forceinline__ void ldx4(uint32_t* d, uint32_t addr) {
    asm volatile("ldmatrix.sync.aligned.m8n8.x4.shared.b16 {%0,%1,%2,%3}, [%4];"
                 : "=r"(d[0]), "=r"(d[1]), "=r"(d[2]), "=r"(d[3]) : "r"(addr));
}
#define MMA_BF16(c, a, b0, b1)                                              \
    asm volatile("mma.sync.aligned.m16n8k16.row.col.f32.bf16.bf16.f32 "     \
                 "{%0,%1,%2,%3}, {%4,%5,%6,%7}, {%8,%9}, {%0,%1,%2,%3};"    \
                 : "+f"((c)[0]), "+f"((c)[1]), "+f"((c)[2]), "+f"((c)[3])   \
                 : "r"((a)[0]), "r"((a)[1]), "r"((a)[2]), "r"((a)[3]),      \
                   "r"(b0), "r"(b1))

// ------------- prep: split hidden into bf16 hi/lo -------------
__global__ void k_hprep(const float* __restrict__ h) {
    size_t i = ((size_t)blockIdx.x * blockDim.x + threadIdx.x) * 4;
    float4 v = *(const float4*)(h + i);
    float vv[4] = {v.x, v.y, v.z, v.w};
    unsigned short hi[4], lo[4];
    #pragma unroll
    for (int k = 0; k < 4; k++) {
        __nv_bfloat16 hb = __float2bfloat16_rn(vv[k]);
        hi[k] = __bfloat16_as_ushort(hb);
        lo[k] = __bfloat16_as_ushort(__float2bfloat16_rn(vv[k] - __bfloat162float(hb)));
    }
    uint2 ph, pl;
    ph.x = (uint32_t)hi[0] | ((uint32_t)hi[1] << 16);
    ph.y = (uint32_t)hi[2] | ((uint32_t)hi[3] << 16);
    pl.x = (uint32_t)lo[0] | ((uint32_t)lo[1] << 16);
    pl.y = (uint32_t)lo[2] | ((uint32_t)lo[3] << 16);
    *(uint2*)(&g_Ahi[i]) = ph;
    *(uint2*)(&g_Alo[i]) = pl;
}

// ------------- prep: conv_w[o][i][s] -> Wt[o][s*512+i], bf16 hi/lo ---------
__global__ void k_wprep(const float* __restrict__ cw) {
    int idx = blockIdx.x * 256 + threadIdx.x;
    if (idx >= HH * KTOT) return;
    int o = idx / KTOT;
    int klin = idx % KTOT;
    int s = klin >> 9, i = klin & 511;
    float v = cw[(o * HH + i) * 3 + s];
    __nv_bfloat16 h = __float2bfloat16_rn(v);
    g_Whi[idx] = h;
    g_Wlo[idx] = __float2bfloat16_rn(v - __bfloat162float(h));
}

// ------------- bf16-split tensor-core GEMM + fused epilogue -------------
// CTA: 128 t x 128 o, K staged 16-wide, 2-stage cp.async pipeline.
__global__ __launch_bounds__(256, 1)
void k_gemm(const float* __restrict__ hidden,
            const float* __restrict__ convb,
            const float* __restrict__ outw) {
    // [stage][tensor: Ahi,Alo,Bhi,Blo][128 rows * ROWPAD]
    __shared__ __align__(16) __nv_bfloat16 sbuf[2][4][128 * ROWPAD];

    const int tid    = threadIdx.x;
    const int lane   = tid & 31;
    const int wid    = tid >> 5;
    const int warp_m = wid >> 2;     // 0..1
    const int warp_n = wid & 3;      // 0..3
    const int b      = blockIdx.x >> 4;
    const int t0     = (blockIdx.x & 15) * 128;
    const int o0     = blockIdx.y * 128;

    const __nv_bfloat16* Ahi = g_Ahi + (size_t)b * TLEN * HH;
    const __nv_bfloat16* Alo = g_Alo + (size_t)b * TLEN * HH;

    const int ldrow = tid >> 1;   // 0..127
    const int ldch  = tid & 1;    // chunk 0/1 (8 bf16 each)

    float acc[4][4][4];
    #pragma unroll
    for (int m = 0; m < 4; m++)
        #pragma unroll
        for (int n = 0; n < 4; n++)
            #pragma unroll
            for (int e = 0; e < 4; e++) acc[m][n][e] = 0.f;

    // ldmatrix lane->address selectors
    const int rowA = lane & 15;
    const int colA = (lane >> 4) << 3;
    const int rowB = (lane & 7) + ((lane >> 4) << 3);
    const int colB = ((lane >> 3) & 1) << 3;

    auto load_stage = [&](int kc, int s) {
        int k0 = kc * TK;
        int sh = k0 >> 9;
        int i0 = k0 & 511;
        int gt = t0 + ldrow + sh - 1;
        bool v = (gt >= 0) && (gt < TLEN);
        int gtc = v ? gt : 0;
        int pb  = v ? 16 : 0;
        const __nv_bfloat16* sAh = Ahi + (size_t)gtc * HH + i0 + ldch * 8;
        const __nv_bfloat16* sAl = Alo + (size_t)gtc * HH + i0 + ldch * 8;
        uint32_t doff = (uint32_t)(ldrow * ROWPAD + ldch * 8);
        cp16(smem_u32(&sbuf[s][0][doff]), sAh, pb);
        cp16(smem_u32(&sbuf[s][1][doff]), sAl, pb);
        const __nv_bfloat16* sWh = g_Whi + (size_t)(o0 + ldrow) * KTOT + k0 + ldch * 8;
        const __nv_bfloat16* sWl = g_Wlo + (size_t)(o0 + ldrow) * KTOT + k0 + ldch * 8;
        cp16(smem_u32(&sbuf[s][2][doff]), sWh, 16);
        cp16(smem_u32(&sbuf[s][3][doff]), sWl, 16);
        asm volatile("cp.async.commit_group;");
    };

    auto compute_stage = [&](int s) {
        uint32_t aH[4][4], aL[4][4], bH[4][2], bL[4][2];
        uint32_t bAh = smem_u32(&sbuf[s][0][0]);
        uint32_t bAl = smem_u32(&sbuf[s][1][0]);
        uint32_t bBh = smem_u32(&sbuf[s][2][0]);
        uint32_t bBl = smem_u32(&sbuf[s][3][0]);
        #pragma unroll
        for (int mf = 0; mf < 4; mf++) {
            uint32_t off = ((warp_m * 64 + mf * 16 + rowA) * ROWPAD + colA) * 2;
            ldx4(aH[mf], bAh + off);
            ldx4(aL[mf], bAl + off);
        }
        #pragma unroll
        for (int nh = 0; nh < 2; nh++) {
            uint32_t off = ((warp_n * 32 + nh * 16 + rowB) * ROWPAD + colB) * 2;
            uint32_t d[4];
            ldx4(d, bBh + off);
            bH[nh*2][0] = d[0]; bH[nh*2][1] = d[1];
            bH[nh*2+1][0] = d[2]; bH[nh*2+1][1] = d[3];
            ldx4(d, bBl + off);
            bL[nh*2][0] = d[0]; bL[nh*2][1] = d[1];
            bL[nh*2+1][0] = d[2]; bL[nh*2+1][1] = d[3];
        }
        #pragma unroll
        for (int mf = 0; mf < 4; mf++)
            #pragma unroll
            for (int nf = 0; nf < 4; nf++) {
                MMA_BF16(acc[mf][nf], aH[mf], bH[nf][0], bH[nf][1]);
                MMA_BF16(acc[mf][nf], aH[mf], bL[nf][0], bL[nf][1]);
                MMA_BF16(acc[mf][nf], aL[mf], bH[nf][0], bH[nf][1]);
            }
    };

    load_stage(0, 0);
    for (int kc = 0; kc < NKC; ++kc) {
        int s = kc & 1;
        if (kc + 1 < NKC) {
            load_stage(kc + 1, s ^ 1);
            asm volatile("cp.async.wait_group 1;");
        } else {
            asm volatile("cp.async.wait_group 0;");
        }
        __syncthreads();
        compute_stage(s);
        __syncthreads();
    }

    // epilogue: y = acc + conv_b + residual; relu; dot out_w; reduce over o-tile
    const int quad = lane >> 2;   // 0..7
    const int pr   = lane & 3;    // 0..3
    const float* hb = hidden + (size_t)b * TLEN * HH;
    float* sred = (float*)&sbuf[0][0][0];   // 128*4 floats

    #pragma unroll
    for (int mf = 0; mf < 4; mf++) {
        int rloc = warp_m * 64 + mf * 16 + quad;
        float sA = 0.f, sB = 0.f;
        #pragma unroll
        for (int nf = 0; nf < 4; nf++) {
            int col = o0 + warp_n * 32 + nf * 8 + pr * 2;
            float2 cb = *(const float2*)(convb + col);
            float2 w  = *(const float2*)(outw + col);
            float2 hA = *(const float2*)(hb + (size_t)(t0 + rloc) * HH + col);
            float2 hB = *(const float2*)(hb + (size_t)(t0 + rloc + 8) * HH + col);
            float y;
            y = fmaxf(acc[mf][nf][0] + cb.x + hA.x, 0.f); sA = fmaf(y, w.x, sA);
            y = fmaxf(acc[mf][nf][1] + cb.y + hA.y, 0.f); sA = fmaf(y, w.y, sA);
            y = fmaxf(acc[mf][nf][2] + cb.x + hB.x, 0.f); sB = fmaf(y, w.x, sB);
            y = fmaxf(acc[mf][nf][3] + cb.y + hB.y, 0.f); sB = fmaf(y, w.y, sB);
        }
        sA += __shfl_xor_sync(0xffffffffu, sA, 1);
        sA += __shfl_xor_sync(0xffffffffu, sA, 2);
        sB += __shfl_xor_sync(0xffffffffu, sB, 1);
        sB += __shfl_xor_sync(0xffffffffu, sB, 2);
        if (pr == 0) {
            sred[rloc * 4 + warp_n]       = sA;
            sred[(rloc + 8) * 4 + warp_n] = sB;
        }
    }
    __syncthreads();
    if (tid < 128) {
        float s = (sred[tid*4+0] + sred[tid*4+1]) + (sred[tid*4+2] + sred[tid*4+3]);
        g_partial[(size_t)(b * TLEN + t0 + tid) * 4 + blockIdx.y] = s;
    }
}

// ---------------- combine partials -> sigmoid -> alpha ----------------
__global__ void k_alpha(const float* __restrict__ mask, const float* __restrict__ outb) {
    int i = blockIdx.x * 256 + threadIdx.x;
    if (i >= BT) return;
    float l = ((g_partial[i*4+0] + g_partial[i*4+1]) +
               (g_partial[i*4+2] + g_partial[i*4+3])) + outb[0];
    float a = 1.f / (1.f + expf(-l));
    a = fmaxf(a, 0.f);
    a *= mask[i];
    g_alpha[i] = a;
}

// ---------------- sequential CIF scan (branchless, pipelined) ----------------
__global__ void k_scan() {
    int b = blockIdx.x;
    if (threadIdx.x != 0) return;
    const float4* al4 = (const float4*)(g_alpha + b * TLEN);
    float4* cur4 = (float4*)(g_cur + b * TLEN);
    int base = b * TLEN;
    float integ = 0.f;
    int j = 0;
    float4 c0 = al4[0], c1 = al4[1];
    #pragma unroll 1
    for (int ch = 0; ch < TLEN / 8; ++ch) {
        float4 n0 = make_float4(0,0,0,0), n1 = make_float4(0,0,0,0);
        if (ch + 1 < TLEN / 8) { n0 = al4[(ch+1)*2]; n1 = al4[(ch+1)*2 + 1]; }
        float av[8] = {c0.x,c0.y,c0.z,c0.w,c1.x,c1.y,c1.z,c1.w};
        float cv[8];
        int tt = ch * 8;
        #pragma unroll
        for (int s = 0; s < 8; s++) {
            float alpha = av[s];
            float dist  = 1.0f - integ;
            integ = integ + alpha;
            bool fire = (integ >= 1.0f);
            float cur = fire ? dist : alpha;
            cv[s] = cur;
            g_fire[base + j] = tt + s;        // unconditional; overwritten if !fire
            g_remv[base + j] = alpha - cur;
            j += fire;
            integ = fire ? integ - 1.0f : integ;
        }
        cur4[ch*2]   = make_float4(cv[0], cv[1], cv[2], cv[3]);
        cur4[ch*2+1] = make_float4(cv[4], cv[5], cv[6], cv[7]);
        c0 = n0; c1 = n1;
    }
    g_nf[b] = j;
}

// ---------------- parallel output gather ----------------
__global__ void k_out(const float* __restrict__ hidden, float* __restrict__ out) {
    int j = blockIdx.x;
    int b = blockIdx.y;
    int c = threadIdx.x << 2;
    const float* hb = hidden + (size_t)b * TLEN * HH;
    float4 acc = make_float4(0.f, 0.f, 0.f, 0.f);
    if (j < g_nf[b]) {
        int tend = g_fire[b * TLEN + j];
        int ts = 0;
        if (j > 0) {
            int tp = g_fire[b * TLEN + j - 1];
            float rv = g_remv[b * TLEN + j - 1];
            float4 h = *(const float4*)(hb + (size_t)tp * HH + c);
            acc.x = rv * h.x; acc.y = rv * h.y; acc.z = rv * h.z; acc.w = rv * h.w;
            ts = tp + 1;
        }
        for (int t = ts; t <= tend; ++t) {
            float w = g_cur[b * TLEN + t];
            float4 h = *(const float4*)(hb + (size_t)t * HH + c);
            acc.x = fmaf(w, h.x, acc.x);
            acc.y = fmaf(w, h.y, acc.y);
            acc.z = fmaf(w, h.z, acc.z);
            acc.w = fmaf(w, h.w, acc.w);
        }
    }
    *(float4*)(out + (size_t)(b * TLEN + j) * HH + c) = acc;
}

extern "C" void kernel_launch(void* const* d_in, const int* in_sizes, int n_in,
                              void* d_out, int out_size) {
    const float* hidden = (const float*)d_in[0];
    const float* mask   = (const float*)d_in[1];
    const float* conv_w = (const float*)d_in[2];
    const float* conv_b = (const float*)d_in[3];
    const float* out_w  = (const float*)d_in[4];
    const float* out_b  = (const float*)d_in[5];
    float* out = (float*)d_out;

    k_hprep<<<(BT*HH/4 + 255)/256, 256>>>(hidden);
    k_wprep<<<(HH*KTOT + 255)/256, 256>>>(conv_w);
    dim3 gg(256, 4);
    k_gemm<<<gg, 256>>>(hidden, conv_b, out_w);
    k_alpha<<<BT/256, 256>>>(mask, out_b);
    k_scan<<<16, 32>>>();
    dim3 go(TLEN, BB);
    k_out<<<go, 128>>>(hidden, out);
}

// round 4
// speedup vs baseline: 1.6592x; 1.0181x over previous
#include <cuda_runtime.h>
#include <cuda_bf16.h>
#include <math.h>
#include <stdint.h>

#define BB 16
#define TLEN 2048
#define HH 512
#define BT (BB*TLEN)
#define KTOT 1536
#define TK 16
#define NKC (KTOT/TK)     // 96
#define ROWPAD 24         // 16 data + 8 pad bf16 per row (48B stride)
#define STAGES 4
#define STAGE_ELEMS (128*ROWPAD)
#define SMEM_BYTES (STAGES*4*STAGE_ELEMS*2)

// static device scratch (no allocations)
__device__ __nv_bfloat16 g_Ahi[(size_t)BT*HH];
__device__ __nv_bfloat16 g_Alo[(size_t)BT*HH];
__device__ __nv_bfloat16 g_Whi[HH*KTOT];   // [o][klin], klin = s*512+i
__device__ __nv_bfloat16 g_Wlo[HH*KTOT];
__device__ float g_partial[BT*4];
__device__ float g_alpha[BT];
__device__ float g_cur[BT];
__device__ float g_remv[BT];
__device__ int   g_fire[BT];
__device__ int   g_nf[BB];

__device__ __forceinline__ uint32_t smem_u32(const void* p) {
    uint32_t r;
    asm("{ .reg .u64 t; cvta.to.shared.u64 t, %1; cvt.u32.u64 %0, t; }"
        : "=r"(r) : "l"(p));
    return r;
}
__device__ __forceinline__ void cp16(uint32_t dst, const void* src, int pb) {
    asm volatile("cp.async.cg.shared.global [%0], [%1], 16, %2;"
                 :: "r"(dst), "l"(src), "r"(pb));
}
__device__ __forceinline__ void ldx4(uint32_t* d, uint32_t addr) {
    asm volatile("ldmatrix.sync.aligned.m8n8.x4.shared.b16 {%0,%1,%2,%3}, [%4];"
                 : "=r"(d[0]), "=r"(d[1]), "=r"(d[2]), "=r"(d[3]) : "r"(addr));
}
#define MMA_BF16(c, a, b0, b1)                                              \
    asm volatile("mma.sync.aligned.m16n8k16.row.col.f32.bf16.bf16.f32 "     \
                 "{%0,%1,%2,%3}, {%4,%5,%6,%7}, {%8,%9}, {%0,%1,%2,%3};"    \
                 : "+f"((c)[0]), "+f"((c)[1]), "+f"((c)[2]), "+f"((c)[3])   \
                 : "r"((a)[0]), "r"((a)[1]), "r"((a)[2]), "r"((a)[3]),      \
                   "r"(b0), "r"(b1))

// ------------- prep: split hidden into bf16 hi/lo -------------
__global__ void k_hprep(const float* __restrict__ h) {
    size_t i = ((size_t)blockIdx.x * blockDim.x + threadIdx.x) * 4;
    float4 v = *(const float4*)(h + i);
    float vv[4] = {v.x, v.y, v.z, v.w};
    unsigned short hi[4], lo[4];
    #pragma unroll
    for (int k = 0; k < 4; k++) {
        __nv_bfloat16 hb = __float2bfloat16_rn(vv[k]);
        hi[k] = __bfloat16_as_ushort(hb);
        lo[k] = __bfloat16_as_ushort(__float2bfloat16_rn(vv[k] - __bfloat162float(hb)));
    }
    uint2 ph, pl;
    ph.x = (uint32_t)hi[0] | ((uint32_t)hi[1] << 16);
    ph.y = (uint32_t)hi[2] | ((uint32_t)hi[3] << 16);
    pl.x = (uint32_t)lo[0] | ((uint32_t)lo[1] << 16);
    pl.y = (uint32_t)lo[2] | ((uint32_t)lo[3] << 16);
    *(uint2*)(&g_Ahi[i]) = ph;
    *(uint2*)(&g_Alo[i]) = pl;
}

// ------------- prep: conv_w[o][i][s] -> Wt[o][s*512+i], bf16 hi/lo ---------
__global__ void k_wprep(const float* __restrict__ cw) {
    int idx = blockIdx.x * 256 + threadIdx.x;
    if (idx >= HH * KTOT) return;
    int o = idx / KTOT;
    int klin = idx % KTOT;
    int s = klin >> 9, i = klin & 511;
    float v = cw[(o * HH + i) * 3 + s];
    __nv_bfloat16 h = __float2bfloat16_rn(v);
    g_Whi[idx] = h;
    g_Wlo[idx] = __float2bfloat16_rn(v - __bfloat162float(h));
}

// ------------- bf16-split tensor-core GEMM + fused epilogue -------------
// CTA: 128 t x 128 o, K staged 16-wide, 4-stage cp.async pipeline, 1 bar/iter.
__global__ __launch_bounds__(256, 1)
void k_gemm(const float* __restrict__ hidden,
            const float* __restrict__ convb,
            const float* __restrict__ outw) {
    extern __shared__ __align__(16) __nv_bfloat16 sbuf[];
    // layout: [stage][tensor: Ahi,Alo,Bhi,Blo][128*ROWPAD]

    const int tid    = threadIdx.x;
    const int lane   = tid & 31;
    const int wid    = tid >> 5;
    const int warp_m = wid >> 2;     // 0..1
    const int warp_n = wid & 3;      // 0..3
    const int b      = blockIdx.x >> 4;
    const int t0     = (blockIdx.x & 15) * 128;
    const int o0     = blockIdx.y * 128;

    const __nv_bfloat16* Ahi = g_Ahi + (size_t)b * TLEN * HH;
    const __nv_bfloat16* Alo = g_Alo + (size_t)b * TLEN * HH;

    const int ldrow = tid >> 1;   // 0..127
    const int ldch  = tid & 1;    // chunk 0/1 (8 bf16 each)

    float acc[4][4][4];
    #pragma unroll
    for (int m = 0; m < 4; m++)
        #pragma unroll
        for (int n = 0; n < 4; n++)
            #pragma unroll
            for (int e = 0; e < 4; e++) acc[m][n][e] = 0.f;

    // ldmatrix lane->address selectors
    const int rowA = lane & 15;
    const int colA = (lane >> 4) << 3;
    const int rowB = (lane & 7) + ((lane >> 4) << 3);
    const int colB = ((lane >> 3) & 1) << 3;

    auto stage_ptr = [&](int s, int tensor) -> __nv_bfloat16* {
        return sbuf + ((size_t)(s * 4 + tensor)) * STAGE_ELEMS;
    };

    auto load_stage = [&](int kc, int s) {
        int k0 = kc * TK;
        int sh = k0 >> 9;
        int i0 = k0 & 511;
        int gt = t0 + ldrow + sh - 1;
        bool v = (gt >= 0) && (gt < TLEN);
        int gtc = v ? gt : 0;
        int pb  = v ? 16 : 0;
        const __nv_bfloat16* sAh = Ahi + (size_t)gtc * HH + i0 + ldch * 8;
        const __nv_bfloat16* sAl = Alo + (size_t)gtc * HH + i0 + ldch * 8;
        uint32_t doff = (uint32_t)(ldrow * ROWPAD + ldch * 8);
        cp16(smem_u32(stage_ptr(s,0) + doff), sAh, pb);
        cp16(smem_u32(stage_ptr(s,1) + doff), sAl, pb);
        const __nv_bfloat16* sWh = g_Whi + (size_t)(o0 + ldrow) * KTOT + k0 + ldch * 8;
        const __nv_bfloat16* sWl = g_Wlo + (size_t)(o0 + ldrow) * KTOT + k0 + ldch * 8;
        cp16(smem_u32(stage_ptr(s,2) + doff), sWh, 16);
        cp16(smem_u32(stage_ptr(s,3) + doff), sWl, 16);
        asm volatile("cp.async.commit_group;");
    };

    auto compute_stage = [&](int s) {
        uint32_t aH[4][4], aL[4][4], bH[4][2], bL[4][2];
        uint32_t bAh = smem_u32(stage_ptr(s,0));
        uint32_t bAl = smem_u32(stage_ptr(s,1));
        uint32_t bBh = smem_u32(stage_ptr(s,2));
        uint32_t bBl = smem_u32(stage_ptr(s,3));
        #pragma unroll
        for (int mf = 0; mf < 4; mf++) {
            uint32_t off = ((warp_m * 64 + mf * 16 + rowA) * ROWPAD + colA) * 2;
            ldx4(aH[mf], bAh + off);
            ldx4(aL[mf], bAl + off);
        }
        #pragma unroll
        for (int nh = 0; nh < 2; nh++) {
            uint32_t off = ((warp_n * 32 + nh * 16 + rowB) * ROWPAD + colB) * 2;
            uint32_t d[4];
            ldx4(d, bBh + off);
            bH[nh*2][0] = d[0]; bH[nh*2][1] = d[1];
            bH[nh*2+1][0] = d[2]; bH[nh*2+1][1] = d[3];
            ldx4(d, bBl + off);
            bL[nh*2][0] = d[0]; bL[nh*2][1] = d[1];
            bL[nh*2+1][0] = d[2]; bL[nh*2+1][1] = d[3];
        }
        #pragma unroll
        for (int mf = 0; mf < 4; mf++)
            #pragma unroll
            for (int nf = 0; nf < 4; nf++) {
                MMA_BF16(acc[mf][nf], aH[mf], bH[nf][0], bH[nf][1]);
                MMA_BF16(acc[mf][nf], aH[mf], bL[nf][0], bL[nf][1]);
                MMA_BF16(acc[mf][nf], aL[mf], bH[nf][0], bH[nf][1]);
            }
    };

    // prologue: 3 stages in flight
    load_stage(0, 0);
    load_stage(1, 1);
    load_stage(2, 2);

    for (int kc = 0; kc < NKC; ++kc) {
        asm volatile("cp.async.wait_group 2;");
        __syncthreads();
        // issue next load before compute so cp.async overlaps the MMA burst
        if (kc + 3 < NKC) {
            load_stage(kc + 3, (kc + 3) & 3);
        } else {
            asm volatile("cp.async.commit_group;");   // keep group accounting
        }
        compute_stage(kc & 3);
    }

    // epilogue: y = acc + conv_b + residual; relu; dot out_w; reduce over o-tile
    const int quad = lane >> 2;   // 0..7
    const int pr   = lane & 3;    // 0..3
    const float* hb = hidden + (size_t)b * TLEN * HH;
    float* sred = (float*)sbuf;   // 128*4 floats
    __syncthreads();

    #pragma unroll
    for (int mf = 0; mf < 4; mf++) {
        int rloc = warp_m * 64 + mf * 16 + quad;
        float sA = 0.f, sB = 0.f;
        #pragma unroll
        for (int nf = 0; nf < 4; nf++) {
            int col = o0 + warp_n * 32 + nf * 8 + pr * 2;
            float2 cb = *(const float2*)(convb + col);
            float2 w  = *(const float2*)(outw + col);
            float2 hA = *(const float2*)(hb + (size_t)(t0 + rloc) * HH + col);
            float2 hB = *(const float2*)(hb + (size_t)(t0 + rloc + 8) * HH + col);
            float y;
            y = fmaxf(acc[mf][nf][0] + cb.x + hA.x, 0.f); sA = fmaf(y, w.x, sA);
            y = fmaxf(acc[mf][nf][1] + cb.y + hA.y, 0.f); sA = fmaf(y, w.y, sA);
            y = fmaxf(acc[mf][nf][2] + cb.x + hB.x, 0.f); sB = fmaf(y, w.x, sB);
            y = fmaxf(acc[mf][nf][3] + cb.y + hB.y, 0.f); sB = fmaf(y, w.y, sB);
        }
        sA += __shfl_xor_sync(0xffffffffu, sA, 1);
        sA += __shfl_xor_sync(0xffffffffu, sA, 2);
        sB += __shfl_xor_sync(0xffffffffu, sB, 1);
        sB += __shfl_xor_sync(0xffffffffu, sB, 2);
        if (pr == 0) {
            sred[rloc * 4 + warp_n]       = sA;
            sred[(rloc + 8) * 4 + warp_n] = sB;
        }
    }
    __syncthreads();
    if (tid < 128) {
        float s = (sred[tid*4+0] + sred[tid*4+1]) + (sred[tid*4+2] + sred[tid*4+3]);
        g_partial[(size_t)(b * TLEN + t0 + tid) * 4 + blockIdx.y] = s;
    }
}

// ---------------- combine partials -> sigmoid -> alpha ----------------
__global__ void k_alpha(const float* __restrict__ mask, const float* __restrict__ outb) {
    int i = blockIdx.x * 256 + threadIdx.x;
    if (i >= BT) return;
    float l = ((g_partial[i*4+0] + g_partial[i*4+1]) +
               (g_partial[i*4+2] + g_partial[i*4+3])) + outb[0];
    float a = 1.f / (1.f + expf(-l));
    a = fmaxf(a, 0.f);
    a *= mask[i];
    g_alpha[i] = a;
}

// ---------------- sequential CIF scan (branchless, pipelined) ----------------
__global__ void k_scan() {
    int b = blockIdx.x;
    if (threadIdx.x != 0) return;
    const float4* al4 = (const float4*)(g_alpha + b * TLEN);
    float4* cur4 = (float4*)(g_cur + b * TLEN);
    int base = b * TLEN;
    float integ = 0.f;
    int j = 0;
    float4 c0 = al4[0], c1 = al4[1];
    #pragma unroll 1
    for (int ch = 0; ch < TLEN / 8; ++ch) {
        float4 n0 = make_float4(0,0,0,0), n1 = make_float4(0,0,0,0);
        if (ch + 1 < TLEN / 8) { n0 = al4[(ch+1)*2]; n1 = al4[(ch+1)*2 + 1]; }
        float av[8] = {c0.x,c0.y,c0.z,c0.w,c1.x,c1.y,c1.z,c1.w};
        float cv[8];
        int tt = ch * 8;
        #pragma unroll
        for (int s = 0; s < 8; s++) {
            float alpha = av[s];
            float dist  = 1.0f - integ;
            integ = integ + alpha;
            bool fire = (integ >= 1.0f);
            float cur = fire ? dist : alpha;
            cv[s] = cur;
            g_fire[base + j] = tt + s;        // unconditional; overwritten if !fire
            g_remv[base + j] = alpha - cur;
            j += fire;
            integ = fire ? integ - 1.0f : integ;
        }
        cur4[ch*2]   = make_float4(cv[0], cv[1], cv[2], cv[3]);
        cur4[ch*2+1] = make_float4(cv[4], cv[5], cv[6], cv[7]);
        c0 = n0; c1 = n1;
    }
    g_nf[b] = j;
}

// ---------------- parallel output gather ----------------
__global__ void k_out(const float* __restrict__ hidden, float* __restrict__ out) {
    int j = blockIdx.x;
    int b = blockIdx.y;
    int c = threadIdx.x << 2;
    const float* hb = hidden + (size_t)b * TLEN * HH;
    float4 acc = make_float4(0.f, 0.f, 0.f, 0.f);
    if (j < g_nf[b]) {
        int tend = g_fire[b * TLEN + j];
        int ts = 0;
        if (j > 0) {
            int tp = g_fire[b * TLEN + j - 1];
            float rv = g_remv[b * TLEN + j - 1];
            float4 h = *(const float4*)(hb + (size_t)tp * HH + c);
            acc.x = rv * h.x; acc.y = rv * h.y; acc.z = rv * h.z; acc.w = rv * h.w;
            ts = tp + 1;
        }
        for (int t = ts; t <= tend; ++t) {
            float w = g_cur[b * TLEN + t];
            float4 h = *(const float4*)(hb + (size_t)t * HH + c);
            acc.x = fmaf(w, h.x, acc.x);
            acc.y = fmaf(w, h.y, acc.y);
            acc.z = fmaf(w, h.z, acc.z);
            acc.w = fmaf(w, h.w, acc.w);
        }
    }
    *(float4*)(out + (size_t)(b * TLEN + j) * HH + c) = acc;
}

extern "C" void kernel_launch(void* const* d_in, const int* in_sizes, int n_in,
                              void* d_out, int out_size) {
    const float* hidden = (const float*)d_in[0];
    const float* mask   = (const float*)d_in[1];
    const float* conv_w = (const float*)d_in[2];
    const float* conv_b = (const float*)d_in[3];
    const float* out_w  = (const float*)d_in[4];
    const float* out_b  = (const float*)d_in[5];
    float* out = (float*)d_out;

    cudaFuncSetAttribute(k_gemm, cudaFuncAttributeMaxDynamicSharedMemorySize, SMEM_BYTES);

    k_hprep<<<(BT*HH/4 + 255)/256, 256>>>(hidden);
    k_wprep<<<(HH*KTOT + 255)/256, 256>>>(conv_w);
    dim3 gg(256, 4);
    k_gemm<<<gg, 256, SMEM_BYTES>>>(hidden, conv_b, out_w);
    k_alpha<<<BT/256, 256>>>(mask, out_b);
    k_scan<<<16, 32>>>();
    dim3 go(TLEN, BB);
    k_out<<<go, 128>>>(hidden, out);
}

// round 6
// speedup vs baseline: 2.0248x; 1.2204x over previous
#include <cuda_runtime.h>
#include <cuda_bf16.h>
#include <math.h>
#include <stdint.h>

#define BB 16
#define TLEN 2048
#define HH 512
#define BT (BB*TLEN)
#define KTOT 1536
#define TK 16
#define NKC (KTOT/TK)     // 96
#define ROWPAD 24         // 16 data + 8 pad bf16 per row (48B stride)
#define STAGES 4
#define STAGE_ELEMS (128*ROWPAD)
#define SMEM_BYTES (STAGES*4*STAGE_ELEMS*2)

// static device scratch (no allocations)
__device__ __nv_bfloat16 g_Ahi[(size_t)BT*HH];
__device__ __nv_bfloat16 g_Alo[(size_t)BT*HH];
__device__ __nv_bfloat16 g_Whi[HH*KTOT];   // [o][klin], klin = s*512+i
__device__ __nv_bfloat16 g_Wlo[HH*KTOT];
__device__ float g_partial[BT*4];
__device__ float g_alpha[BT];
__device__ float g_cur[BT];
__device__ float g_remv[BT];
__device__ int   g_fire[BT];
__device__ int   g_nf[BB];

__device__ __forceinline__ uint32_t smem_u32(const void* p) {
    uint32_t r;
    asm("{ .reg .u64 t; cvta.to.shared.u64 t, %1; cvt.u32.u64 %0, t; }"
        : "=r"(r) : "l"(p));
    return r;
}
__device__ __forceinline__ void cp16(uint32_t dst, const void* src, int pb) {
    asm volatile("cp.async.cg.shared.global [%0], [%1], 16, %2;"
                 :: "r"(dst), "l"(src), "r"(pb));
}
__device__ __forceinline__ void ldx4(uint32_t* d, uint32_t addr) {
    asm volatile("ldmatrix.sync.aligned.m8n8.x4.shared.b16 {%0,%1,%2,%3}, [%4];"
                 : "=r"(d[0]), "=r"(d[1]), "=r"(d[2]), "=r"(d[3]) : "r"(addr));
}
#define MMA_BF16(c, a, b0, b1)                                              \
    asm volatile("mma.sync.aligned.m16n8k16.row.col.f32.bf16.bf16.f32 "     \
                 "{%0,%1,%2,%3}, {%4,%5,%6,%7}, {%8,%9}, {%0,%1,%2,%3};"    \
                 : "+f"((c)[0]), "+f"((c)[1]), "+f"((c)[2]), "+f"((c)[3])   \
                 : "r"((a)[0]), "r"((a)[1]), "r"((a)[2]), "r"((a)[3]),      \
                   "r"(b0), "r"(b1))

// ------------- prep: split hidden into bf16 hi/lo -------------
__global__ void k_hprep(const float* __restrict__ h) {
    size_t i = ((size_t)blockIdx.x * blockDim.x + threadIdx.x) * 4;
    float4 v = *(const float4*)(h + i);
    float vv[4] = {v.x, v.y, v.z, v.w};
    unsigned short hi[4], lo[4];
    #pragma unroll
    for (int k = 0; k < 4; k++) {
        __nv_bfloat16 hb = __float2bfloat16_rn(vv[k]);
        hi[k] = __bfloat16_as_ushort(hb);
        lo[k] = __bfloat16_as_ushort(__float2bfloat16_rn(vv[k] - __bfloat162float(hb)));
    }
    uint2 ph, pl;
    ph.x = (uint32_t)hi[0] | ((uint32_t)hi[1] << 16);
    ph.y = (uint32_t)hi[2] | ((uint32_t)hi[3] << 16);
    pl.x = (uint32_t)lo[0] | ((uint32_t)lo[1] << 16);
    pl.y = (uint32_t)lo[2] | ((uint32_t)lo[3] << 16);
    *(uint2*)(&g_Ahi[i]) = ph;
    *(uint2*)(&g_Alo[i]) = pl;
}

// ------------- prep: conv_w[o][i][s] -> Wt[o][s*512+i], bf16 hi/lo ---------
__global__ void k_wprep(const float* __restrict__ cw) {
    int idx = blockIdx.x * 256 + threadIdx.x;
    if (idx >= HH * KTOT) return;
    int o = idx / KTOT;
    int klin = idx % KTOT;
    int s = klin >> 9, i = klin & 511;
    float v = cw[(o * HH + i) * 3 + s];
    __nv_bfloat16 h = __float2bfloat16_rn(v);
    g_Whi[idx] = h;
    g_Wlo[idx] = __float2bfloat16_rn(v - __bfloat162float(h));
}

// ------------- bf16-split tensor-core GEMM + fused epilogue -------------
// CTA: 128 t x 128 o, K staged 16-wide, 4-stage cp.async pipeline, occ 2.
__global__ __launch_bounds__(256, 2)
void k_gemm(const float* __restrict__ hidden,
            const float* __restrict__ convb,
            const float* __restrict__ outw) {
    extern __shared__ __align__(16) __nv_bfloat16 sbuf[];
    // layout: [stage][tensor: Ahi,Alo,Bhi,Blo][128*ROWPAD]

    const int tid    = threadIdx.x;
    const int lane   = tid & 31;
    const int wid    = tid >> 5;
    const int warp_m = wid >> 2;     // 0..1
    const int warp_n = wid & 3;      // 0..3
    const int b      = blockIdx.x >> 4;
    const int t0     = (blockIdx.x & 15) * 128;
    const int o0     = blockIdx.y * 128;

    const __nv_bfloat16* Ahi = g_Ahi + (size_t)b * TLEN * HH;
    const __nv_bfloat16* Alo = g_Alo + (size_t)b * TLEN * HH;

    const int ldrow = tid >> 1;   // 0..127
    const int ldch  = tid & 1;    // chunk 0/1 (8 bf16 each)

    float acc[4][4][4];
    #pragma unroll
    for (int m = 0; m < 4; m++)
        #pragma unroll
        for (int n = 0; n < 4; n++)
            #pragma unroll
            for (int e = 0; e < 4; e++) acc[m][n][e] = 0.f;

    // ldmatrix lane->address selectors
    const int rowA = lane & 15;
    const int colA = (lane >> 4) << 3;
    const int rowB = (lane & 7) + ((lane >> 4) << 3);
    const int colB = ((lane >> 3) & 1) << 3;

    auto stage_ptr = [&](int s, int tensor) -> __nv_bfloat16* {
        return sbuf + ((size_t)(s * 4 + tensor)) * STAGE_ELEMS;
    };

    auto load_stage = [&](int kc, int s) {
        int k0 = kc * TK;
        int sh = k0 >> 9;
        int i0 = k0 & 511;
        int gt = t0 + ldrow + sh - 1;
        bool v = (gt >= 0) && (gt < TLEN);
        int gtc = v ? gt : 0;
        int pb  = v ? 16 : 0;
        const __nv_bfloat16* sAh = Ahi + (size_t)gtc * HH + i0 + ldch * 8;
        const __nv_bfloat16* sAl = Alo + (size_t)gtc * HH + i0 + ldch * 8;
        uint32_t doff = (uint32_t)(ldrow * ROWPAD + ldch * 8);
        cp16(smem_u32(stage_ptr(s,0) + doff), sAh, pb);
        cp16(smem_u32(stage_ptr(s,1) + doff), sAl, pb);
        const __nv_bfloat16* sWh = g_Whi + (size_t)(o0 + ldrow) * KTOT + k0 + ldch * 8;
        const __nv_bfloat16* sWl = g_Wlo + (size_t)(o0 + ldrow) * KTOT + k0 + ldch * 8;
        cp16(smem_u32(stage_ptr(s,2) + doff), sWh, 16);
        cp16(smem_u32(stage_ptr(s,3) + doff), sWl, 16);
        asm volatile("cp.async.commit_group;");
    };

    auto compute_stage = [&](int s) {
        uint32_t aH[4][4], aL[4][4], bH[4][2], bL[4][2];
        uint32_t bAh = smem_u32(stage_ptr(s,0));
        uint32_t bAl = smem_u32(stage_ptr(s,1));
        uint32_t bBh = smem_u32(stage_ptr(s,2));
        uint32_t bBl = smem_u32(stage_ptr(s,3));
        #pragma unroll
        for (int mf = 0; mf < 4; mf++) {
            uint32_t off = ((warp_m * 64 + mf * 16 + rowA) * ROWPAD + colA) * 2;
            ldx4(aH[mf], bAh + off);
            ldx4(aL[mf], bAl + off);
        }
        #pragma unroll
        for (int nh = 0; nh < 2; nh++) {
            uint32_t off = ((warp_n * 32 + nh * 16 + rowB) * ROWPAD + colB) * 2;
            uint32_t d[4];
            ldx4(d, bBh + off);
            bH[nh*2][0] = d[0]; bH[nh*2][1] = d[1];
            bH[nh*2+1][0] = d[2]; bH[nh*2+1][1] = d[3];
            ldx4(d, bBl + off);
            bL[nh*2][0] = d[0]; bL[nh*2][1] = d[1];
            bL[nh*2+1][0] = d[2]; bL[nh*2+1][1] = d[3];
        }
        // term-major order: maximal independence between consecutive MMAs;
        // per-accumulator order is still H*H -> H*L -> L*H (bit-identical).
        #pragma unroll
        for (int mf = 0; mf < 4; mf++)
            #pragma unroll
            for (int nf = 0; nf < 4; nf++)
                MMA_BF16(acc[mf][nf], aH[mf], bH[nf][0], bH[nf][1]);
        #pragma unroll
        for (int mf = 0; mf < 4; mf++)
            #pragma unroll
            for (int nf = 0; nf < 4; nf++)
                MMA_BF16(acc[mf][nf], aH[mf], bL[nf][0], bL[nf][1]);
        #pragma unroll
        for (int mf = 0; mf < 4; mf++)
            #pragma unroll
            for (int nf = 0; nf < 4; nf++)
                MMA_BF16(acc[mf][nf], aL[mf], bH[nf][0], bH[nf][1]);
    };

    // prologue: 3 stages in flight
    load_stage(0, 0);
    load_stage(1, 1);
    load_stage(2, 2);

    for (int kc = 0; kc < NKC; ++kc) {
        asm volatile("cp.async.wait_group 2;");
        __syncthreads();
        // issue next load before compute so cp.async overlaps the MMA burst
        if (kc + 3 < NKC) {
            load_stage(kc + 3, (kc + 3) & 3);
        } else {
            asm volatile("cp.async.commit_group;");   // keep group accounting
        }
        compute_stage(kc & 3);
    }

    // epilogue: y = acc + conv_b + residual; relu; dot out_w; reduce over o-tile
    const int quad = lane >> 2;   // 0..7
    const int pr   = lane & 3;    // 0..3
    const float* hb = hidden + (size_t)b * TLEN * HH;
    float* sred = (float*)sbuf;   // 128*4 floats
    __syncthreads();

    #pragma unroll
    for (int mf = 0; mf < 4; mf++) {
        int rloc = warp_m * 64 + mf * 16 + quad;
        float sA = 0.f, sB = 0.f;
        #pragma unroll
        for (int nf = 0; nf < 4; nf++) {
            int col = o0 + warp_n * 32 + nf * 8 + pr * 2;
            float2 cb = *(const float2*)(convb + col);
            float2 w  = *(const float2*)(outw + col);
            float2 hA = *(const float2*)(hb + (size_t)(t0 + rloc) * HH + col);
            float2 hB = *(const float2*)(hb + (size_t)(t0 + rloc + 8) * HH + col);
            float y;
            y = fmaxf(acc[mf][nf][0] + cb.x + hA.x, 0.f); sA = fmaf(y, w.x, sA);
            y = fmaxf(acc[mf][nf][1] + cb.y + hA.y, 0.f); sA = fmaf(y, w.y, sA);
            y = fmaxf(acc[mf][nf][2] + cb.x + hB.x, 0.f); sB = fmaf(y, w.x, sB);
            y = fmaxf(acc[mf][nf][3] + cb.y + hB.y, 0.f); sB = fmaf(y, w.y, sB);
        }
        sA += __shfl_xor_sync(0xffffffffu, sA, 1);
        sA += __shfl_xor_sync(0xffffffffu, sA, 2);
        sB += __shfl_xor_sync(0xffffffffu, sB, 1);
        sB += __shfl_xor_sync(0xffffffffu, sB, 2);
        if (pr == 0) {
            sred[rloc * 4 + warp_n]       = sA;
            sred[(rloc + 8) * 4 + warp_n] = sB;
        }
    }
    __syncthreads();
    if (tid < 128) {
        float s = (sred[tid*4+0] + sred[tid*4+1]) + (sred[tid*4+2] + sred[tid*4+3]);
        g_partial[(size_t)(b * TLEN + t0 + tid) * 4 + blockIdx.y] = s;
    }
}

// ---------------- combine partials -> sigmoid -> alpha ----------------
__global__ void k_alpha(const float* __restrict__ mask, const float* __restrict__ outb) {
    int i = blockIdx.x * 256 + threadIdx.x;
    if (i >= BT) return;
    float l = ((g_partial[i*4+0] + g_partial[i*4+1]) +
               (g_partial[i*4+2] + g_partial[i*4+3])) + outb[0];
    float a = 1.f / (1.f + expf(-l));
    a = fmaxf(a, 0.f);
    a *= mask[i];
    g_alpha[i] = a;
}

// ---------------- sequential CIF scan (branchless, pipelined) ----------------
__global__ void k_scan() {
    int b = blockIdx.x;
    if (threadIdx.x != 0) return;
    const float4* al4 = (const float4*)(g_alpha + b * TLEN);
    float4* cur4 = (float4*)(g_cur + b * TLEN);
    int base = b * TLEN;
    float integ = 0.f;
    int j = 0;
    float4 c0 = al4[0], c1 = al4[1];
    #pragma unroll 1
    for (int ch = 0; ch < TLEN / 8; ++ch) {
        float4 n0 = make_float4(0,0,0,0), n1 = make_float4(0,0,0,0);
        if (ch + 1 < TLEN / 8) { n0 = al4[(ch+1)*2]; n1 = al4[(ch+1)*2 + 1]; }
        float av[8] = {c0.x,c0.y,c0.z,c0.w,c1.x,c1.y,c1.z,c1.w};
        float cv[8];
        int tt = ch * 8;
        #pragma unroll
        for (int s = 0; s < 8; s++) {
            float alpha = av[s];
            float dist  = 1.0f - integ;
            integ = integ + alpha;
            bool fire = (integ >= 1.0f);
            float cur = fire ? dist : alpha;
            cv[s] = cur;
            g_fire[base + j] = tt + s;        // unconditional; overwritten if !fire
            g_remv[base + j] = alpha - cur;
            j += fire;
            integ = fire ? integ - 1.0f : integ;
        }
        cur4[ch*2]   = make_float4(cv[0], cv[1], cv[2], cv[3]);
        cur4[ch*2+1] = make_float4(cv[4], cv[5], cv[6], cv[7]);
        c0 = n0; c1 = n1;
    }
    g_nf[b] = j;
}

// ---------------- parallel output gather ----------------
__global__ void k_out(const float* __restrict__ hidden, float* __restrict__ out) {
    int j = blockIdx.x;
    int b = blockIdx.y;
    int c = threadIdx.x << 2;
    const float* hb = hidden + (size_t)b * TLEN * HH;
    float4 acc = make_float4(0.f, 0.f, 0.f, 0.f);
    if (j < g_nf[b]) {
        int tend = g_fire[b * TLEN + j];
        int ts = 0;
        if (j > 0) {
            int tp = g_fire[b * TLEN + j - 1];
            float rv = g_remv[b * TLEN + j - 1];
            float4 h = *(const float4*)(hb + (size_t)tp * HH + c);
            acc.x = rv * h.x; acc.y = rv * h.y; acc.z = rv * h.z; acc.w = rv * h.w;
            ts = tp + 1;
        }
        for (int t = ts; t <= tend; ++t) {
            float w = g_cur[b * TLEN + t];
            float4 h = *(const float4*)(hb + (size_t)t * HH + c);
            acc.x = fmaf(w, h.x, acc.x);
            acc.y = fmaf(w, h.y, acc.y);
            acc.z = fmaf(w, h.z, acc.z);
            acc.w = fmaf(w, h.w, acc.w);
        }
    }
    *(float4*)(out + (size_t)(b * TLEN + j) * HH + c) = acc;
}

extern "C" void kernel_launch(void* const* d_in, const int* in_sizes, int n_in,
                              void* d_out, int out_size) {
    const float* hidden = (const float*)d_in[0];
    const float* mask   = (const float*)d_in[1];
    const float* conv_w = (const float*)d_in[2];
    const float* conv_b = (const float*)d_in[3];
    const float* out_w  = (const float*)d_in[4];
    const float* out_b  = (const float*)d_in[5];
    float* out = (float*)d_out;

    cudaFuncSetAttribute(k_gemm, cudaFuncAttributeMaxDynamicSharedMemorySize, SMEM_BYTES);

    k_hprep<<<(BT*HH/4 + 255)/256, 256>>>(hidden);
    k_wprep<<<(HH*KTOT + 255)/256, 256>>>(conv_w);
    dim3 gg(256, 4);
    k_gemm<<<gg, 256, SMEM_BYTES>>>(hidden, conv_b, out_w);
    k_alpha<<<BT/256, 256>>>(mask, out_b);
    k_scan<<<16, 32>>>();
    dim3 go(TLEN, BB);
    k_out<<<go, 128>>>(hidden, out);
}

// round 7
// speedup vs baseline: 2.2121x; 1.0925x over previous
#include <cuda_runtime.h>
#include <cuda_bf16.h>
#include <math.h>
#include <stdint.h>

#define BB 16
#define TLEN 2048
#define HH 512
#define BT (BB*TLEN)
#define KTOT 1536
#define NCH 32                // 32 channel-chunks of 16
#define NS 3                  // ring depth
// per-stage smem layout (bytes from stage base):
//   Ahi: 130 rows x 48B          [0, 6240)
//   Alo:                          [6240, 12480)
//   B  : 6 tensors (s*2+h) x 128 rows x 32B  [12480, 37056)
#define ST_ALO  6240
#define ST_B    12480
#define B_T     4096
#define STAGE_B 37120
#define DSMEM   (NS*STAGE_B)   // 111360

// static device scratch (no allocations)
__device__ __nv_bfloat16 g_Ahi[(size_t)BT*HH];
__device__ __nv_bfloat16 g_Alo[(size_t)BT*HH];
__device__ __nv_bfloat16 g_Whi[HH*KTOT];   // [o][klin], klin = s*512+i
__device__ __nv_bfloat16 g_Wlo[HH*KTOT];
__device__ float g_partial[BT*4];
__device__ float g_alpha[BT];
__device__ float g_cur[BT];
__device__ float g_remv[BT];
__device__ int   g_fire[BT];
__device__ int   g_nf[BB];

__device__ __forceinline__ uint32_t smem_u32(const void* p) {
    uint32_t r;
    asm("{ .reg .u64 t; cvta.to.shared.u64 t, %1; cvt.u32.u64 %0, t; }"
        : "=r"(r) : "l"(p));
    return r;
}
__device__ __forceinline__ void cp16(uint32_t dst, const void* src, int pb) {
    asm volatile("cp.async.cg.shared.global [%0], [%1], 16, %2;"
                 :: "r"(dst), "l"(src), "r"(pb));
}
__device__ __forceinline__ void ldx4(uint32_t* d, uint32_t addr) {
    asm volatile("ldmatrix.sync.aligned.m8n8.x4.shared.b16 {%0,%1,%2,%3}, [%4];"
                 : "=r"(d[0]), "=r"(d[1]), "=r"(d[2]), "=r"(d[3]) : "r"(addr));
}
#define MMA_BF16(c, a, b0, b1)                                              \
    asm volatile("mma.sync.aligned.m16n8k16.row.col.f32.bf16.bf16.f32 "     \
                 "{%0,%1,%2,%3}, {%4,%5,%6,%7}, {%8,%9}, {%0,%1,%2,%3};"    \
                 : "+f"((c)[0]), "+f"((c)[1]), "+f"((c)[2]), "+f"((c)[3])   \
                 : "r"((a)[0]), "r"((a)[1]), "r"((a)[2]), "r"((a)[3]),      \
                   "r"(b0), "r"(b1))

// ------------- prep: split hidden into bf16 hi/lo -------------
__global__ void k_hprep(const float* __restrict__ h) {
    size_t i = ((size_t)blockIdx.x * blockDim.x + threadIdx.x) * 4;
    float4 v = *(const float4*)(h + i);
    float vv[4] = {v.x, v.y, v.z, v.w};
    unsigned short hi[4], lo[4];
    #pragma unroll
    for (int k = 0; k < 4; k++) {
        __nv_bfloat16 hb = __float2bfloat16_rn(vv[k]);
        hi[k] = __bfloat16_as_ushort(hb);
        lo[k] = __bfloat16_as_ushort(__float2bfloat16_rn(vv[k] - __bfloat162float(hb)));
    }
    uint2 ph, pl;
    ph.x = (uint32_t)hi[0] | ((uint32_t)hi[1] << 16);
    ph.y = (uint32_t)hi[2] | ((uint32_t)hi[3] << 16);
    pl.x = (uint32_t)lo[0] | ((uint32_t)lo[1] << 16);
    pl.y = (uint32_t)lo[2] | ((uint32_t)lo[3] << 16);
    *(uint2*)(&g_Ahi[i]) = ph;
    *(uint2*)(&g_Alo[i]) = pl;
}

// ------------- prep: conv_w[o][i][s] -> Wt[o][s*512+i], bf16 hi/lo ---------
__global__ void k_wprep(const float* __restrict__ cw) {
    int idx = blockIdx.x * 256 + threadIdx.x;
    if (idx >= HH * KTOT) return;
    int o = idx / KTOT;
    int klin = idx % KTOT;
    int s = klin >> 9, i = klin & 511;
    float v = cw[(o * HH + i) * 3 + s];
    __nv_bfloat16 h = __float2bfloat16_rn(v);
    g_Whi[idx] = h;
    g_Wlo[idx] = __float2bfloat16_rn(v - __bfloat162float(h));
}

// ------------- bf16-split tensor-core GEMM, chunk-major/shift-inner -------
// CTA: 128 t x 128 o. 32 chunk-iters; each stage holds a 130-row A tile
// (all 3 shifts) + B for all 3 shifts. 3-stage cp.async ring, occ 2.
__global__ __launch_bounds__(256, 2)
void k_gemm(const float* __restrict__ hidden,
            const float* __restrict__ convb,
            const float* __restrict__ outw) {
    extern __shared__ __align__(16) unsigned char sbuf[];

    const int tid    = threadIdx.x;
    const int lane   = tid & 31;
    const int wid    = tid >> 5;
    const int warp_m = wid >> 2;     // 0..1
    const int warp_n = wid & 3;      // 0..3
    const int b      = blockIdx.x >> 4;
    const int t0     = (blockIdx.x & 15) * 128;
    const int o0     = blockIdx.y * 128;

    const __nv_bfloat16* Ahi = g_Ahi + (size_t)b * TLEN * HH;
    const __nv_bfloat16* Alo = g_Alo + (size_t)b * TLEN * HH;
    const uint32_t sb = smem_u32(sbuf);

    float acc[4][4][4];
    #pragma unroll
    for (int m = 0; m < 4; m++)
        #pragma unroll
        for (int n = 0; n < 4; n++)
            #pragma unroll
            for (int e = 0; e < 4; e++) acc[m][n][e] = 0.f;

    // ldmatrix lane->address selectors
    const int rowA = lane & 15;
    const int colA = (lane >> 4) << 3;
    const int rowB = (lane & 7) + ((lane >> 4) << 3);
    const int colB = ((lane >> 3) & 1) << 3;

    // B thread mapping (fixed per thread)
    const int browp = tid >> 1;        // 0..127
    const int bchk  = tid & 1;         // 16B chunk

    auto load_stage = [&](int c) {
        const uint32_t st = sb + (uint32_t)(c % NS) * STAGE_B;
        const int i0 = c * 16;
        // A: 130 rows x 2 tensors x 2 chunks = 520 ops
        #pragma unroll
        for (int j = 0; j < 3; j++) {
            int a = tid + j * 256;
            if (a < 520) {
                int chunk  = a & 1;
                int tensor = (a >> 1) & 1;
                int row    = a >> 2;            // 0..129
                int gt = t0 - 1 + row;
                bool v = (gt >= 0) && (gt < TLEN);
                int gtc = v ? gt : 0;
                int pb  = v ? 16 : 0;
                const __nv_bfloat16* src =
                    (tensor ? Alo : Ahi) + (size_t)gtc * HH + i0 + chunk * 8;
                cp16(st + tensor * ST_ALO + row * 48 + chunk * 16, src, pb);
            }
        }
        // B: 6 tensors (s,h) x 128 rows x 2 chunks = 1536 ops
        #pragma unroll
        for (int j = 0; j < 6; j++) {
            int s = j >> 1, h = j & 1;
            const __nv_bfloat16* src =
                (h ? g_Wlo : g_Whi) + (size_t)(o0 + browp) * KTOT + s * 512 + i0 + bchk * 8;
            cp16(st + ST_B + j * B_T + browp * 32 + bchk * 16, src, 16);
        }
        asm volatile("cp.async.commit_group;");
    };

    auto compute_stage = [&](int c) {
        const uint32_t st = sb + (uint32_t)(c % NS) * STAGE_B;
        #pragma unroll
        for (int s = 0; s < 3; s++) {
            uint32_t aH[4][4], aL[4][4], bH[4][2], bL[4][2];
            #pragma unroll
            for (int mf = 0; mf < 4; mf++) {
                uint32_t off = (uint32_t)((warp_m * 64 + mf * 16 + rowA + s) * 48 + colA * 2);
                ldx4(aH[mf], st + off);
                ldx4(aL[mf], st + ST_ALO + off);
            }
            #pragma unroll
            for (int nh = 0; nh < 2; nh++) {
                uint32_t offb = (uint32_t)((warp_n * 32 + nh * 16 + rowB) * 32 + colB * 2);
                uint32_t d[4];
                ldx4(d, st + ST_B + (s * 2 + 0) * B_T + offb);
                bH[nh*2][0] = d[0]; bH[nh*2][1] = d[1];
                bH[nh*2+1][0] = d[2]; bH[nh*2+1][1] = d[3];
                ldx4(d, st + ST_B + (s * 2 + 1) * B_T + offb);
                bL[nh*2][0] = d[0]; bL[nh*2][1] = d[1];
                bL[nh*2+1][0] = d[2]; bL[nh*2+1][1] = d[3];
            }
            // term-major: per-accumulator order stays H*H -> H*L -> L*H
            #pragma unroll
            for (int mf = 0; mf < 4; mf++)
                #pragma unroll
                for (int nf = 0; nf < 4; nf++)
                    MMA_BF16(acc[mf][nf], aH[mf], bH[nf][0], bH[nf][1]);
            #pragma unroll
            for (int mf = 0; mf < 4; mf++)
                #pragma unroll
                for (int nf = 0; nf < 4; nf++)
                    MMA_BF16(acc[mf][nf], aH[mf], bL[nf][0], bL[nf][1]);
            #pragma unroll
            for (int mf = 0; mf < 4; mf++)
                #pragma unroll
                for (int nf = 0; nf < 4; nf++)
                    MMA_BF16(acc[mf][nf], aL[mf], bH[nf][0], bH[nf][1]);
        }
    };

    // prologue: fill ring
    load_stage(0);
    load_stage(1);
    load_stage(2);

    for (int c = 0; c < NCH; ++c) {
        asm volatile("cp.async.wait_group 2;");
        __syncthreads();
        compute_stage(c);
        __syncthreads();
        if (c + NS < NCH) {
            load_stage(c + NS);
        } else {
            asm volatile("cp.async.commit_group;");   // keep group accounting
        }
    }

    // epilogue: y = acc + conv_b + residual; relu; dot out_w; reduce over o-tile
    const int quad = lane >> 2;   // 0..7
    const int pr   = lane & 3;    // 0..3
    const float* hb = hidden + (size_t)b * TLEN * HH;
    float* sred = (float*)sbuf;   // 128*4 floats

    #pragma unroll
    for (int mf = 0; mf < 4; mf++) {
        int rloc = warp_m * 64 + mf * 16 + quad;
        float sA = 0.f, sB = 0.f;
        #pragma unroll
        for (int nf = 0; nf < 4; nf++) {
            int col = o0 + warp_n * 32 + nf * 8 + pr * 2;
            float2 cb = *(const float2*)(convb + col);
            float2 w  = *(const float2*)(outw + col);
            float2 hA = *(const float2*)(hb + (size_t)(t0 + rloc) * HH + col);
            float2 hB = *(const float2*)(hb + (size_t)(t0 + rloc + 8) * HH + col);
            float y;
            y = fmaxf(acc[mf][nf][0] + cb.x + hA.x, 0.f); sA = fmaf(y, w.x, sA);
            y = fmaxf(acc[mf][nf][1] + cb.y + hA.y, 0.f); sA = fmaf(y, w.y, sA);
            y = fmaxf(acc[mf][nf][2] + cb.x + hB.x, 0.f); sB = fmaf(y, w.x, sB);
            y = fmaxf(acc[mf][nf][3] + cb.y + hB.y, 0.f); sB = fmaf(y, w.y, sB);
        }
        sA += __shfl_xor_sync(0xffffffffu, sA, 1);
        sA += __shfl_xor_sync(0xffffffffu, sA, 2);
        sB += __shfl_xor_sync(0xffffffffu, sB, 1);
        sB += __shfl_xor_sync(0xffffffffu, sB, 2);
        if (pr == 0) {
            sred[rloc * 4 + warp_n]       = sA;
            sred[(rloc + 8) * 4 + warp_n] = sB;
        }
    }
    __syncthreads();
    if (tid < 128) {
        float s = (sred[tid*4+0] + sred[tid*4+1]) + (sred[tid*4+2] + sred[tid*4+3]);
        g_partial[(size_t)(b * TLEN + t0 + tid) * 4 + blockIdx.y] = s;
    }
}

// ---------------- combine partials -> sigmoid -> alpha ----------------
__global__ void k_alpha(const float* __restrict__ mask, const float* __restrict__ outb) {
    int i = blockIdx.x * 256 + threadIdx.x;
    if (i >= BT) return;
    float l = ((g_partial[i*4+0] + g_partial[i*4+1]) +
               (g_partial[i*4+2] + g_partial[i*4+3])) + outb[0];
    float a = 1.f / (1.f + expf(-l));
    a = fmaxf(a, 0.f);
    a *= mask[i];
    g_alpha[i] = a;
}

// ---------------- sequential CIF scan (branchless, pipelined) ----------------
__global__ void k_scan() {
    int b = blockIdx.x;
    if (threadIdx.x != 0) return;
    const float4* al4 = (const float4*)(g_alpha + b * TLEN);
    float4* cur4 = (float4*)(g_cur + b * TLEN);
    int base = b * TLEN;
    float integ = 0.f;
    int j = 0;
    float4 c0 = al4[0], c1 = al4[1];
    #pragma unroll 1
    for (int ch = 0; ch < TLEN / 8; ++ch) {
        float4 n0 = make_float4(0,0,0,0), n1 = make_float4(0,0,0,0);
        if (ch + 1 < TLEN / 8) { n0 = al4[(ch+1)*2]; n1 = al4[(ch+1)*2 + 1]; }
        float av[8] = {c0.x,c0.y,c0.z,c0.w,c1.x,c1.y,c1.z,c1.w};
        float cv[8];
        int tt = ch * 8;
        #pragma unroll
        for (int s = 0; s < 8; s++) {
            float alpha = av[s];
            float dist  = 1.0f - integ;
            integ = integ + alpha;
            bool fire = (integ >= 1.0f);
            float cur = fire ? dist : alpha;
            cv[s] = cur;
            g_fire[base + j] = tt + s;        // unconditional; overwritten if !fire
            g_remv[base + j] = alpha - cur;
            j += fire;
            integ = fire ? integ - 1.0f : integ;
        }
        cur4[ch*2]   = make_float4(cv[0], cv[1], cv[2], cv[3]);
        cur4[ch*2+1] = make_float4(cv[4], cv[5], cv[6], cv[7]);
        c0 = n0; c1 = n1;
    }
    g_nf[b] = j;
}

// ---------------- parallel output gather ----------------
__global__ void k_out(const float* __restrict__ hidden, float* __restrict__ out) {
    int j = blockIdx.x;
    int b = blockIdx.y;
    int c = threadIdx.x << 2;
    const float* hb = hidden + (size_t)b * TLEN * HH;
    float4 acc = make_float4(0.f, 0.f, 0.f, 0.f);
    if (j < g_nf[b]) {
        int tend = g_fire[b * TLEN + j];
        int ts = 0;
        if (j > 0) {
            int tp = g_fire[b * TLEN + j - 1];
            float rv = g_remv[b * TLEN + j - 1];
            float4 h = *(const float4*)(hb + (size_t)tp * HH + c);
            acc.x = rv * h.x; acc.y = rv * h.y; acc.z = rv * h.z; acc.w = rv * h.w;
            ts = tp + 1;
        }
        for (int t = ts; t <= tend; ++t) {
            float w = g_cur[b * TLEN + t];
            float4 h = *(const float4*)(hb + (size_t)t * HH + c);
            acc.x = fmaf(w, h.x, acc.x);
            acc.y = fmaf(w, h.y, acc.y);
            acc.z = fmaf(w, h.z, acc.z);
            acc.w = fmaf(w, h.w, acc.w);
        }
    }
    *(float4*)(out + (size_t)(b * TLEN + j) * HH + c) = acc;
}

extern "C" void kernel_launch(void* const* d_in, const int* in_sizes, int n_in,
                              void* d_out, int out_size) {
    const float* hidden = (const float*)d_in[0];
    const float* mask   = (const float*)d_in[1];
    const float* conv_w = (const float*)d_in[2];
    const float* conv_b = (const float*)d_in[3];
    const float* out_w  = (const float*)d_in[4];
    const float* out_b  = (const float*)d_in[5];
    float* out = (float*)d_out;

    cudaFuncSetAttribute(k_gemm, cudaFuncAttributeMaxDynamicSharedMemorySize, DSMEM);

    k_hprep<<<(BT*HH/4 + 255)/256, 256>>>(hidden);
    k_wprep<<<(HH*KTOT + 255)/256, 256>>>(conv_w);
    dim3 gg(256, 4);
    k_gemm<<<gg, 256, DSMEM>>>(hidden, conv_b, out_w);
    k_alpha<<<BT/256, 256>>>(mask, out_b);
    k_scan<<<16, 32>>>();
    dim3 go(TLEN, BB);
    k_out<<<go, 128>>>(hidden, out);
}

// round 8
// speedup vs baseline: 2.2272x; 1.0068x over previous
#include <cuda_runtime.h>
#include <cuda_bf16.h>
#include <math.h>
#include <stdint.h>

#define BB 16
#define TLEN 2048
#define HH 512
#define BT (BB*TLEN)
#define KTOT 1536
#define NCH 32                // 32 channel-chunks of 16
#define NS 3                  // ring depth
// per-stage smem layout (bytes from stage base):
//   Ahi: 130 rows x 48B          [0, 6240)
//   Alo:                          [6240, 12480)
//   B  : 6 tensors (s*2+h) x 128 rows x 32B  [12480, 37056)
#define ST_ALO  6240
#define ST_B    12480
#define B_T     4096
#define STAGE_B 37120
#define DSMEM   (NS*STAGE_B)   // 111360

// static device scratch (no allocations)
__device__ __nv_bfloat16 g_Ahi[(size_t)BT*HH];
__device__ __nv_bfloat16 g_Alo[(size_t)BT*HH];
__device__ __nv_bfloat16 g_Whi[HH*KTOT];   // [o][klin], klin = s*512+i
__device__ __nv_bfloat16 g_Wlo[HH*KTOT];
__device__ float g_partial[BT*4];
__device__ float g_alpha[BT];
__device__ float g_cur[BT];
__device__ float g_remv[BT];
__device__ int   g_fire[BT];
__device__ int   g_nf[BB];

__device__ __forceinline__ uint32_t smem_u32(const void* p) {
    uint32_t r;
    asm("{ .reg .u64 t; cvta.to.shared.u64 t, %1; cvt.u32.u64 %0, t; }"
        : "=r"(r) : "l"(p));
    return r;
}
__device__ __forceinline__ void cp16(uint32_t dst, const void* src, int pb) {
    asm volatile("cp.async.cg.shared.global [%0], [%1], 16, %2;"
                 :: "r"(dst), "l"(src), "r"(pb));
}
__device__ __forceinline__ void ldx4(uint32_t* d, uint32_t addr) {
    asm volatile("ldmatrix.sync.aligned.m8n8.x4.shared.b16 {%0,%1,%2,%3}, [%4];"
                 : "=r"(d[0]), "=r"(d[1]), "=r"(d[2]), "=r"(d[3]) : "r"(addr));
}
#define MMA_BF16(c, a, b0, b1)                                              \
    asm volatile("mma.sync.aligned.m16n8k16.row.col.f32.bf16.bf16.f32 "     \
                 "{%0,%1,%2,%3}, {%4,%5,%6,%7}, {%8,%9}, {%0,%1,%2,%3};"    \
                 : "+f"((c)[0]), "+f"((c)[1]), "+f"((c)[2]), "+f"((c)[3])   \
                 : "r"((a)[0]), "r"((a)[1]), "r"((a)[2]), "r"((a)[3]),      \
                   "r"(b0), "r"(b1))

// ------------- prep: split hidden into bf16 hi/lo -------------
__global__ void k_hprep(const float* __restrict__ h) {
    size_t i = ((size_t)blockIdx.x * blockDim.x + threadIdx.x) * 4;
    float4 v = *(const float4*)(h + i);
    float vv[4] = {v.x, v.y, v.z, v.w};
    unsigned short hi[4], lo[4];
    #pragma unroll
    for (int k = 0; k < 4; k++) {
        __nv_bfloat16 hb = __float2bfloat16_rn(vv[k]);
        hi[k] = __bfloat16_as_ushort(hb);
        lo[k] = __bfloat16_as_ushort(__float2bfloat16_rn(vv[k] - __bfloat162float(hb)));
    }
    uint2 ph, pl;
    ph.x = (uint32_t)hi[0] | ((uint32_t)hi[1] << 16);
    ph.y = (uint32_t)hi[2] | ((uint32_t)hi[3] << 16);
    pl.x = (uint32_t)lo[0] | ((uint32_t)lo[1] << 16);
    pl.y = (uint32_t)lo[2] | ((uint32_t)lo[3] << 16);
    *(uint2*)(&g_Ahi[i]) = ph;
    *(uint2*)(&g_Alo[i]) = pl;
}

// ------------- prep: conv_w[o][i][s] -> Wt[o][s*512+i], bf16 hi/lo ---------
__global__ void k_wprep(const float* __restrict__ cw) {
    int idx = blockIdx.x * 256 + threadIdx.x;
    if (idx >= HH * KTOT) return;
    int o = idx / KTOT;
    int klin = idx % KTOT;
    int s = klin >> 9, i = klin & 511;
    float v = cw[(o * HH + i) * 3 + s];
    __nv_bfloat16 h = __float2bfloat16_rn(v);
    g_Whi[idx] = h;
    g_Wlo[idx] = __float2bfloat16_rn(v - __bfloat162float(h));
}

// ------------- bf16-split tensor-core GEMM, chunk-major/shift-inner -------
// CTA: 128 t x 128 o. 32 chunk-iters; 3-stage ring with depth-2 lookahead
// and ONE barrier per chunk. occ 2.
__global__ __launch_bounds__(256, 2)
void k_gemm(const float* __restrict__ hidden,
            const float* __restrict__ convb,
            const float* __restrict__ outw) {
    extern __shared__ __align__(16) unsigned char sbuf[];

    const int tid    = threadIdx.x;
    const int lane   = tid & 31;
    const int wid    = tid >> 5;
    const int warp_m = wid >> 2;     // 0..1
    const int warp_n = wid & 3;      // 0..3
    const int b      = blockIdx.x >> 4;
    const int t0     = (blockIdx.x & 15) * 128;
    const int o0     = blockIdx.y * 128;

    const __nv_bfloat16* Ahi = g_Ahi + (size_t)b * TLEN * HH;
    const __nv_bfloat16* Alo = g_Alo + (size_t)b * TLEN * HH;
    const uint32_t sb = smem_u32(sbuf);

    float acc[4][4][4];
    #pragma unroll
    for (int m = 0; m < 4; m++)
        #pragma unroll
        for (int n = 0; n < 4; n++)
            #pragma unroll
            for (int e = 0; e < 4; e++) acc[m][n][e] = 0.f;

    // ldmatrix lane->address selectors
    const int rowA = lane & 15;
    const int colA = (lane >> 4) << 3;
    const int rowB = (lane & 7) + ((lane >> 4) << 3);
    const int colB = ((lane >> 3) & 1) << 3;

    // B thread mapping (fixed per thread)
    const int browp = tid >> 1;        // 0..127
    const int bchk  = tid & 1;         // 16B chunk

    auto load_stage = [&](int c) {
        const uint32_t st = sb + (uint32_t)(c % NS) * STAGE_B;
        const int i0 = c * 16;
        // A: 130 rows x 2 tensors x 2 chunks = 520 ops
        #pragma unroll
        for (int j = 0; j < 3; j++) {
            int a = tid + j * 256;
            if (a < 520) {
                int chunk  = a & 1;
                int tensor = (a >> 1) & 1;
                int row    = a >> 2;            // 0..129
                int gt = t0 - 1 + row;
                bool v = (gt >= 0) && (gt < TLEN);
                int gtc = v ? gt : 0;
                int pb  = v ? 16 : 0;
                const __nv_bfloat16* src =
                    (tensor ? Alo : Ahi) + (size_t)gtc * HH + i0 + chunk * 8;
                cp16(st + tensor * ST_ALO + row * 48 + chunk * 16, src, pb);
            }
        }
        // B: 6 tensors (s,h) x 128 rows x 2 chunks = 1536 ops
        #pragma unroll
        for (int j = 0; j < 6; j++) {
            int s = j >> 1, h = j & 1;
            const __nv_bfloat16* src =
                (h ? g_Wlo : g_Whi) + (size_t)(o0 + browp) * KTOT + s * 512 + i0 + bchk * 8;
            cp16(st + ST_B + j * B_T + browp * 32 + bchk * 16, src, 16);
        }
        asm volatile("cp.async.commit_group;");
    };

    auto compute_stage = [&](int c) {
        const uint32_t st = sb + (uint32_t)(c % NS) * STAGE_B;
        #pragma unroll
        for (int s = 0; s < 3; s++) {
            uint32_t aH[4][4], aL[4][4], bH[4][2], bL[4][2];
            #pragma unroll
            for (int mf = 0; mf < 4; mf++) {
                uint32_t off = (uint32_t)((warp_m * 64 + mf * 16 + rowA + s) * 48 + colA * 2);
                ldx4(aH[mf], st + off);
                ldx4(aL[mf], st + ST_ALO + off);
            }
            #pragma unroll
            for (int nh = 0; nh < 2; nh++) {
                uint32_t offb = (uint32_t)((warp_n * 32 + nh * 16 + rowB) * 32 + colB * 2);
                uint32_t d[4];
                ldx4(d, st + ST_B + (s * 2 + 0) * B_T + offb);
                bH[nh*2][0] = d[0]; bH[nh*2][1] = d[1];
                bH[nh*2+1][0] = d[2]; bH[nh*2+1][1] = d[3];
                ldx4(d, st + ST_B + (s * 2 + 1) * B_T + offb);
                bL[nh*2][0] = d[0]; bL[nh*2][1] = d[1];
                bL[nh*2+1][0] = d[2]; bL[nh*2+1][1] = d[3];
            }
            // term-major: per-accumulator order stays H*H -> H*L -> L*H
            #pragma unroll
            for (int mf = 0; mf < 4; mf++)
                #pragma unroll
                for (int nf = 0; nf < 4; nf++)
                    MMA_BF16(acc[mf][nf], aH[mf], bH[nf][0], bH[nf][1]);
            #pragma unroll
            for (int mf = 0; mf < 4; mf++)
                #pragma unroll
                for (int nf = 0; nf < 4; nf++)
                    MMA_BF16(acc[mf][nf], aH[mf], bL[nf][0], bL[nf][1]);
            #pragma unroll
            for (int mf = 0; mf < 4; mf++)
                #pragma unroll
                for (int nf = 0; nf < 4; nf++)
                    MMA_BF16(acc[mf][nf], aL[mf], bH[nf][0], bH[nf][1]);
        }
    };

    // prologue: depth-2 lookahead
    load_stage(0);
    load_stage(1);

    for (int c = 0; c < NCH; ++c) {
        // slot c is complete once only group c+1 is allowed pending
        asm volatile("cp.async.wait_group 1;");
        __syncthreads();   // also guarantees compute(c-1) fully done in all warps
        // load(c+2) targets slot (c-1)%3 — its reader compute(c-1) finished
        // before the barrier above. Empty commit keeps group recency exact.
        if (c + 2 < NCH) {
            load_stage(c + 2);
        } else {
            asm volatile("cp.async.commit_group;");
        }
        compute_stage(c);
    }

    // epilogue: y = acc + conv_b + residual; relu; dot out_w; reduce over o-tile
    const int quad = lane >> 2;   // 0..7
    const int pr   = lane & 3;    // 0..3
    const float* hb = hidden + (size_t)b * TLEN * HH;
    float* sred = (float*)sbuf;   // 128*4 floats
    __syncthreads();

    #pragma unroll
    for (int mf = 0; mf < 4; mf++) {
        int rloc = warp_m * 64 + mf * 16 + quad;
        float sA = 0.f, sB = 0.f;
        #pragma unroll
        for (int nf = 0; nf < 4; nf++) {
            int col = o0 + warp_n * 32 + nf * 8 + pr * 2;
            float2 cb = *(const float2*)(convb + col);
            float2 w  = *(const float2*)(outw + col);
            float2 hA = *(const float2*)(hb + (size_t)(t0 + rloc) * HH + col);
            float2 hB = *(const float2*)(hb + (size_t)(t0 + rloc + 8) * HH + col);
            float y;
            y = fmaxf(acc[mf][nf][0] + cb.x + hA.x, 0.f); sA = fmaf(y, w.x, sA);
            y = fmaxf(acc[mf][nf][1] + cb.y + hA.y, 0.f); sA = fmaf(y, w.y, sA);
            y = fmaxf(acc[mf][nf][2] + cb.x + hB.x, 0.f); sB = fmaf(y, w.x, sB);
            y = fmaxf(acc[mf][nf][3] + cb.y + hB.y, 0.f); sB = fmaf(y, w.y, sB);
        }
        sA += __shfl_xor_sync(0xffffffffu, sA, 1);
        sA += __shfl_xor_sync(0xffffffffu, sA, 2);
        sB += __shfl_xor_sync(0xffffffffu, sB, 1);
        sB += __shfl_xor_sync(0xffffffffu, sB, 2);
        if (pr == 0) {
            sred[rloc * 4 + warp_n]       = sA;
            sred[(rloc + 8) * 4 + warp_n] = sB;
        }
    }
    __syncthreads();
    if (tid < 128) {
        float s = (sred[tid*4+0] + sred[tid*4+1]) + (sred[tid*4+2] + sred[tid*4+3]);
        g_partial[(size_t)(b * TLEN + t0 + tid) * 4 + blockIdx.y] = s;
    }
}

// ---------------- combine partials -> sigmoid -> alpha ----------------
__global__ void k_alpha(const float* __restrict__ mask, const float* __restrict__ outb) {
    int i = blockIdx.x * 256 + threadIdx.x;
    if (i >= BT) return;
    float l = ((g_partial[i*4+0] + g_partial[i*4+1]) +
               (g_partial[i*4+2] + g_partial[i*4+3])) + outb[0];
    float a = 1.f / (1.f + expf(-l));
    a = fmaxf(a, 0.f);
    a *= mask[i];
    g_alpha[i] = a;
}

// ---------------- sequential CIF scan (branchless, pipelined) ----------------
__global__ void k_scan() {
    int b = blockIdx.x;
    if (threadIdx.x != 0) return;
    const float4* al4 = (const float4*)(g_alpha + b * TLEN);
    float4* cur4 = (float4*)(g_cur + b * TLEN);
    int base = b * TLEN;
    float integ = 0.f;
    int j = 0;
    float4 c0 = al4[0], c1 = al4[1];
    #pragma unroll 1
    for (int ch = 0; ch < TLEN / 8; ++ch) {
        float4 n0 = make_float4(0,0,0,0), n1 = make_float4(0,0,0,0);
        if (ch + 1 < TLEN / 8) { n0 = al4[(ch+1)*2]; n1 = al4[(ch+1)*2 + 1]; }
        float av[8] = {c0.x,c0.y,c0.z,c0.w,c1.x,c1.y,c1.z,c1.w};
        float cv[8];
        int tt = ch * 8;
        #pragma unroll
        for (int s = 0; s < 8; s++) {
            float alpha = av[s];
            float dist  = 1.0f - integ;
            integ = integ + alpha;
            bool fire = (integ >= 1.0f);
            float cur = fire ? dist : alpha;
            cv[s] = cur;
            g_fire[base + j] = tt + s;        // unconditional; overwritten if !fire
            g_remv[base + j] = alpha - cur;
            j += fire;
            integ = fire ? integ - 1.0f : integ;
        }
        cur4[ch*2]   = make_float4(cv[0], cv[1], cv[2], cv[3]);
        cur4[ch*2+1] = make_float4(cv[4], cv[5], cv[6], cv[7]);
        c0 = n0; c1 = n1;
    }
    g_nf[b] = j;
}

// ---------------- parallel output gather ----------------
__global__ void k_out(const float* __restrict__ hidden, float* __restrict__ out) {
    int j = blockIdx.x;
    int b = blockIdx.y;
    int c = threadIdx.x << 2;
    const float* hb = hidden + (size_t)b * TLEN * HH;
    float4 acc = make_float4(0.f, 0.f, 0.f, 0.f);
    if (j < g_nf[b]) {
        int tend = g_fire[b * TLEN + j];
        int ts = 0;
        if (j > 0) {
            int tp = g_fire[b * TLEN + j - 1];
            float rv = g_remv[b * TLEN + j - 1];
            float4 h = *(const float4*)(hb + (size_t)tp * HH + c);
            acc.x = rv * h.x; acc.y = rv * h.y; acc.z = rv * h.z; acc.w = rv * h.w;
            ts = tp + 1;
        }
        for (int t = ts; t <= tend; ++t) {
            float w = g_cur[b * TLEN + t];
            float4 h = *(const float4*)(hb + (size_t)t * HH + c);
            acc.x = fmaf(w, h.x, acc.x);
            acc.y = fmaf(w, h.y, acc.y);
            acc.z = fmaf(w, h.z, acc.z);
            acc.w = fmaf(w, h.w, acc.w);
        }
    }
    *(float4*)(out + (size_t)(b * TLEN + j) * HH + c) = acc;
}

extern "C" void kernel_launch(void* const* d_in, const int* in_sizes, int n_in,
                              void* d_out, int out_size) {
    const float* hidden = (const float*)d_in[0];
    const float* mask   = (const float*)d_in[1];
    const float* conv_w = (const float*)d_in[2];
    const float* conv_b = (const float*)d_in[3];
    const float* out_w  = (const float*)d_in[4];
    const float* out_b  = (const float*)d_in[5];
    float* out = (float*)d_out;

    cudaFuncSetAttribute(k_gemm, cudaFuncAttributeMaxDynamicSharedMemorySize, DSMEM);

    k_hprep<<<(BT*HH/4 + 255)/256, 256>>>(hidden);
    k_wprep<<<(HH*KTOT + 255)/256, 256>>>(conv_w);
    dim3 gg(256, 4);
    k_gemm<<<gg, 256, DSMEM>>>(hidden, conv_b, out_w);
    k_alpha<<<BT/256, 256>>>(mask, out_b);
    k_scan<<<16, 32>>>();
    dim3 go(TLEN, BB);
    k_out<<<go, 128>>>(hidden, out);
}

// round 10
// speedup vs baseline: 2.2590x; 1.0143x over previous
#include <cuda_runtime.h>
#include <cuda_bf16.h>
#include <math.h>
#include <stdint.h>

#define BB 16
#define TLEN 2048
#define HH 512
#define BT (BB*TLEN)
#define KTOT 1536
#define NCH 32                // 32 channel-chunks of 16
#define NS 3                  // ring depth
// per-stage smem layout (bytes from stage base):
//   Ahi: 130 rows x 48B          [0, 6240)
//   Alo:                          [6240, 12480)
//   B  : 6 tensors (s*2+h) x 128 rows x 32B (chunk-XOR swizzled)
#define ST_ALO  6240
#define ST_B    12480
#define B_T     4096
#define STAGE_B (ST_B + 6*B_T)   // 37056
#define DSMEM   (NS*STAGE_B)     // 111168

// static device scratch (no allocations)
__device__ __nv_bfloat16 g_Ahi[(size_t)BT*HH];
__device__ __nv_bfloat16 g_Alo[(size_t)BT*HH];
__device__ __nv_bfloat16 g_Whi[HH*KTOT];   // [o][klin], klin = s*512+i
__device__ __nv_bfloat16 g_Wlo[HH*KTOT];
__device__ float g_partial[BT*4];
__device__ float g_alpha[BT];
__device__ float g_cur[BT];
__device__ float g_remv[BT];
__device__ int   g_fire[BT];
__device__ int   g_nf[BB];

__device__ __forceinline__ uint32_t smem_u32(const void* p) {
    uint32_t r;
    asm("{ .reg .u64 t; cvta.to.shared.u64 t, %1; cvt.u32.u64 %0, t; }"
        : "=r"(r) : "l"(p));
    return r;
}
__device__ __forceinline__ void cp16(uint32_t dst, const void* src, int pb) {
    asm volatile("cp.async.cg.shared.global [%0], [%1], 16, %2;"
                 :: "r"(dst), "l"(src), "r"(pb));
}
__device__ __forceinline__ void ldx4(uint32_t* d, uint32_t addr) {
    asm volatile("ldmatrix.sync.aligned.m8n8.x4.shared.b16 {%0,%1,%2,%3}, [%4];"
                 : "=r"(d[0]), "=r"(d[1]), "=r"(d[2]), "=r"(d[3]) : "r"(addr));
}
#define MMA_BF16(c, a, b0, b1)                                              \
    asm volatile("mma.sync.aligned.m16n8k16.row.col.f32.bf16.bf16.f32 "     \
                 "{%0,%1,%2,%3}, {%4,%5,%6,%7}, {%8,%9}, {%0,%1,%2,%3};"    \
                 : "+f"((c)[0]), "+f"((c)[1]), "+f"((c)[2]), "+f"((c)[3])   \
                 : "r"((a)[0]), "r"((a)[1]), "r"((a)[2]), "r"((a)[3]),      \
                   "r"(b0), "r"(b1))

// ------------- prep: split hidden into bf16 hi/lo -------------
__global__ void k_hprep(const float* __restrict__ h) {
    size_t i = ((size_t)blockIdx.x * blockDim.x + threadIdx.x) * 4;
    float4 v = *(const float4*)(h + i);
    float vv[4] = {v.x, v.y, v.z, v.w};
    unsigned short hi[4], lo[4];
    #pragma unroll
    for (int k = 0; k < 4; k++) {
        __nv_bfloat16 hb = __float2bfloat16_rn(vv[k]);
        hi[k] = __bfloat16_as_ushort(hb);
        lo[k] = __bfloat16_as_ushort(__float2bfloat16_rn(vv[k] - __bfloat162float(hb)));
    }
    uint2 ph, pl;
    ph.x = (uint32_t)hi[0] | ((uint32_t)hi[1] << 16);
    ph.y = (uint32_t)hi[2] | ((uint32_t)hi[3] << 16);
    pl.x = (uint32_t)lo[0] | ((uint32_t)lo[1] << 16);
    pl.y = (uint32_t)lo[2] | ((uint32_t)lo[3] << 16);
    *(uint2*)(&g_Ahi[i]) = ph;
    *(uint2*)(&g_Alo[i]) = pl;
}

// ------------- prep: conv_w[o][i][s] -> Wt[o][s*512+i], bf16 hi/lo ---------
__global__ void k_wprep(const float* __restrict__ cw) {
    int idx = blockIdx.x * 256 + threadIdx.x;
    if (idx >= HH * KTOT) return;
    int o = idx / KTOT;
    int klin = idx % KTOT;
    int s = klin >> 9, i = klin & 511;
    float v = cw[(o * HH + i) * 3 + s];
    __nv_bfloat16 h = __float2bfloat16_rn(v);
    g_Whi[idx] = h;
    g_Wlo[idx] = __float2bfloat16_rn(v - __bfloat162float(h));
}

// ------------- bf16-split tensor-core GEMM, chunk-major/shift-inner -------
// CTA: 128 t x 128 o. 32 chunk-iters; 3-stage ring, depth-2 lookahead,
// one barrier/chunk, occ 2. B rows chunk-XOR swizzled -> conflict-free LDSM.
__global__ __launch_bounds__(256, 2)
void k_gemm(const float* __restrict__ hidden,
            const float* __restrict__ convb,
            const float* __restrict__ outw) {
    extern __shared__ __align__(16) unsigned char sbuf[];

    const int tid    = threadIdx.x;
    const int lane   = tid & 31;
    const int wid    = tid >> 5;
    const int warp_m = wid >> 2;     // 0..1
    const int warp_n = wid & 3;      // 0..3
    const int b      = blockIdx.x >> 4;
    const int t0     = (blockIdx.x & 15) * 128;
    const int o0     = blockIdx.y * 128;

    const __nv_bfloat16* Ahi = g_Ahi + (size_t)b * TLEN * HH;
    const __nv_bfloat16* Alo = g_Alo + (size_t)b * TLEN * HH;
    const uint32_t sb = smem_u32(sbuf);

    float acc[4][4][4];
    #pragma unroll
    for (int m = 0; m < 4; m++)
        #pragma unroll
        for (int n = 0; n < 4; n++)
            #pragma unroll
            for (int e = 0; e < 4; e++) acc[m][n][e] = 0.f;

    // ldmatrix lane->address selectors
    const int rowA = lane & 15;
    const int colA = (lane >> 4) << 3;
    const int rowB = (lane & 7) + ((lane >> 4) << 3);   // 0..15
    const int chunkB = (lane >> 3) & 1;                  // 16B chunk select
    // chunk-XOR swizzle: physical chunk = chunk ^ ((row>>2)&1)
    const uint32_t rdoff = (uint32_t)(rowB * 32 + ((chunkB ^ ((rowB >> 2) & 1)) << 4));

    // B thread mapping (fixed per thread)
    const int browp = tid >> 1;        // 0..127
    const int bchk  = tid & 1;         // 16B chunk
    const uint32_t bwr = (uint32_t)(browp * 32 + ((bchk ^ ((browp >> 2) & 1)) << 4));

    auto load_stage = [&](int c) {
        const uint32_t st = sb + (uint32_t)(c % NS) * STAGE_B;
        const int i0 = c * 16;
        // A: 130 rows x 2 tensors x 2 chunks = 520 ops
        #pragma unroll
        for (int j = 0; j < 3; j++) {
            int a = tid + j * 256;
            if (a < 520) {
                int chunk  = a & 1;
                int tensor = (a >> 1) & 1;
                int row    = a >> 2;            // 0..129
                int gt = t0 - 1 + row;
                bool v = (gt >= 0) && (gt < TLEN);
                int gtc = v ? gt : 0;
                int pb  = v ? 16 : 0;
                const __nv_bfloat16* src =
                    (tensor ? Alo : Ahi) + (size_t)gtc * HH + i0 + chunk * 8;
                cp16(st + tensor * ST_ALO + row * 48 + chunk * 16, src, pb);
            }
        }
        // B: 6 tensors (s,h) x 128 rows x 2 chunks = 1536 ops
        #pragma unroll
        for (int j = 0; j < 6; j++) {
            int s = j >> 1, h = j & 1;
            const __nv_bfloat16* src =
                (h ? g_Wlo : g_Whi) + (size_t)(o0 + browp) * KTOT + s * 512 + i0 + bchk * 8;
            cp16(st + ST_B + j * B_T + bwr, src, 16);
        }
        asm volatile("cp.async.commit_group;");
    };

    auto compute_stage = [&](int c) {
        const uint32_t st = sb + (uint32_t)(c % NS) * STAGE_B;
        #pragma unroll
        for (int s = 0; s < 3; s++) {
            uint32_t aH[4][4], aL[4][4], bH[4][2], bL[4][2];
            #pragma unroll
            for (int mf = 0; mf < 4; mf++) {
                uint32_t off = (uint32_t)((warp_m * 64 + mf * 16 + rowA + s) * 48 + colA * 2);
                ldx4(aH[mf], st + off);
                ldx4(aL[mf], st + ST_ALO + off);
            }
            #pragma unroll
            for (int nh = 0; nh < 2; nh++) {
                // matrix base rows are multiples of 16 -> phase pattern identical
                uint32_t offb = (uint32_t)((warp_n * 32 + nh * 16) * 32) + rdoff;
                uint32_t d[4];
                ldx4(d, st + ST_B + (s * 2 + 0) * B_T + offb);
                bH[nh*2][0] = d[0]; bH[nh*2][1] = d[1];
                bH[nh*2+1][0] = d[2]; bH[nh*2+1][1] = d[3];
                ldx4(d, st + ST_B + (s * 2 + 1) * B_T + offb);
                bL[nh*2][0] = d[0]; bL[nh*2][1] = d[1];
                bL[nh*2+1][0] = d[2]; bL[nh*2+1][1] = d[3];
            }
            // term-major: per-accumulator order stays H*H -> H*L -> L*H
            #pragma unroll
            for (int mf = 0; mf < 4; mf++)
                #pragma unroll
                for (int nf = 0; nf < 4; nf++)
                    MMA_BF16(acc[mf][nf], aH[mf], bH[nf][0], bH[nf][1]);
            #pragma unroll
            for (int mf = 0; mf < 4; mf++)
                #pragma unroll
                for (int nf = 0; nf < 4; nf++)
                    MMA_BF16(acc[mf][nf], aH[mf], bL[nf][0], bL[nf][1]);
            #pragma unroll
            for (int mf = 0; mf < 4; mf++)
                #pragma unroll
                for (int nf = 0; nf < 4; nf++)
                    MMA_BF16(acc[mf][nf], aL[mf], bH[nf][0], bH[nf][1]);
        }
    };

    // prologue: depth-2 lookahead
    load_stage(0);
    load_stage(1);

    for (int c = 0; c < NCH; ++c) {
        asm volatile("cp.async.wait_group 1;");
        __syncthreads();
        if (c + 2 < NCH) {
            load_stage(c + 2);
        } else {
            asm volatile("cp.async.commit_group;");
        }
        compute_stage(c);
    }

    // epilogue: y = acc + conv_b + residual; relu; dot out_w; reduce over o-tile
    const int quad = lane >> 2;   // 0..7
    const int pr   = lane & 3;    // 0..3
    const float* hb = hidden + (size_t)b * TLEN * HH;
    float* sred = (float*)sbuf;   // 128*4 floats
    __syncthreads();

    #pragma unroll
    for (int mf = 0; mf < 4; mf++) {
        int rloc = warp_m * 64 + mf * 16 + quad;
        float sA = 0.f, sB = 0.f;
        #pragma unroll
        for (int nf = 0; nf < 4; nf++) {
            int col = o0 + warp_n * 32 + nf * 8 + pr * 2;
            float2 cb = *(const float2*)(convb + col);
            float2 w  = *(const float2*)(outw + col);
            float2 hA = *(const float2*)(hb + (size_t)(t0 + rloc) * HH + col);
            float2 hB = *(const float2*)(hb + (size_t)(t0 + rloc + 8) * HH + col);
            float y;
            y = fmaxf(acc[mf][nf][0] + cb.x + hA.x, 0.f); sA = fmaf(y, w.x, sA);
            y = fmaxf(acc[mf][nf][1] + cb.y + hA.y, 0.f); sA = fmaf(y, w.y, sA);
            y = fmaxf(acc[mf][nf][2] + cb.x + hB.x, 0.f); sB = fmaf(y, w.x, sB);
            y = fmaxf(acc[mf][nf][3] + cb.y + hB.y, 0.f); sB = fmaf(y, w.y, sB);
        }
        sA += __shfl_xor_sync(0xffffffffu, sA, 1);
        sA += __shfl_xor_sync(0xffffffffu, sA, 2);
        sB += __shfl_xor_sync(0xffffffffu, sB, 1);
        sB += __shfl_xor_sync(0xffffffffu, sB, 2);
        if (pr == 0) {
            sred[rloc * 4 + warp_n]       = sA;
            sred[(rloc + 8) * 4 + warp_n] = sB;
        }
    }
    __syncthreads();
    if (tid < 128) {
        float s = (sred[tid*4+0] + sred[tid*4+1]) + (sred[tid*4+2] + sred[tid*4+3]);
        g_partial[(size_t)(b * TLEN + t0 + tid) * 4 + blockIdx.y] = s;
    }
}

// ---------------- combine partials -> sigmoid -> alpha ----------------
__global__ void k_alpha(const float* __restrict__ mask, const float* __restrict__ outb) {
    int i = blockIdx.x * 256 + threadIdx.x;
    if (i >= BT) return;
    float l = ((g_partial[i*4+0] + g_partial[i*4+1]) +
               (g_partial[i*4+2] + g_partial[i*4+3])) + outb[0];
    float a = 1.f / (1.f + expf(-l));
    a = fmaxf(a, 0.f);
    a *= mask[i];
    g_alpha[i] = a;
}

// ---------------- sequential CIF scan (branchless, pipelined) ----------------
__global__ void k_scan() {
    int b = blockIdx.x;
    if (threadIdx.x != 0) return;
    const float4* al4 = (const float4*)(g_alpha + b * TLEN);
    float4* cur4 = (float4*)(g_cur + b * TLEN);
    int base = b * TLEN;
    float integ = 0.f;
    int j = 0;
    float4 c0 = al4[0], c1 = al4[1];
    #pragma unroll 1
    for (int ch = 0; ch < TLEN / 8; ++ch) {
        float4 n0 = make_float4(0,0,0,0), n1 = make_float4(0,0,0,0);
        if (ch + 1 < TLEN / 8) { n0 = al4[(ch+1)*2]; n1 = al4[(ch+1)*2 + 1]; }
        float av[8] = {c0.x,c0.y,c0.z,c0.w,c1.x,c1.y,c1.z,c1.w};
        float cv[8];
        int tt = ch * 8;
        #pragma unroll
        for (int s = 0; s < 8; s++) {
            float alpha = av[s];
            float dist  = 1.0f - integ;
            integ = integ + alpha;
            bool fire = (integ >= 1.0f);
            float cur = fire ? dist : alpha;
            cv[s] = cur;
            g_fire[base + j] = tt + s;        // unconditional; overwritten if !fire
            g_remv[base + j] = alpha - cur;
            j += fire;
            integ = fire ? integ - 1.0f : integ;
        }
        cur4[ch*2]   = make_float4(cv[0], cv[1], cv[2], cv[3]);
        cur4[ch*2+1] = make_float4(cv[4], cv[5], cv[6], cv[7]);
        c0 = n0; c1 = n1;
    }
    g_nf[b] = j;
}

// ---------------- parallel output gather ----------------
__global__ void k_out(const float* __restrict__ hidden, float* __restrict__ out) {
    int j = blockIdx.x;
    int b = blockIdx.y;
    int c = threadIdx.x << 2;
    const float* hb = hidden + (size_t)b * TLEN * HH;
    float4 acc = make_float4(0.f, 0.f, 0.f, 0.f);
    if (j < g_nf[b]) {
        int tend = g_fire[b * TLEN + j];
        int ts = 0;
        if (j > 0) {
            int tp = g_fire[b * TLEN + j - 1];
            float rv = g_remv[b * TLEN + j - 1];
            float4 h = *(const float4*)(hb + (size_t)tp * HH + c);
            acc.x = rv * h.x; acc.y = rv * h.y; acc.z = rv * h.z; acc.w = rv * h.w;
            ts = tp + 1;
        }
        for (int t = ts; t <= tend; ++t) {
            float w = g_cur[b * TLEN + t];
            float4 h = *(const float4*)(hb + (size_t)t * HH + c);
            acc.x = fmaf(w, h.x, acc.x);
            acc.y = fmaf(w, h.y, acc.y);
            acc.z = fmaf(w, h.z, acc.z);
            acc.w = fmaf(w, h.w, acc.w);
        }
    }
    *(float4*)(out + (size_t)(b * TLEN + j) * HH + c) = acc;
}

extern "C" void kernel_launch(void* const* d_in, const int* in_sizes, int n_in,
                              void* d_out, int out_size) {
    const float* hidden = (const float*)d_in[0];
    const float* mask   = (const float*)d_in[1];
    const float* conv_w = (const float*)d_in[2];
    const float* conv_b = (const float*)d_in[3];
    const float* out_w  = (const float*)d_in[4];
    const float* out_b  = (const float*)d_in[5];
    float* out = (float*)d_out;

    cudaFuncSetAttribute(k_gemm, cudaFuncAttributeMaxDynamicSharedMemorySize, DSMEM);

    k_hprep<<<(BT*HH/4 + 255)/256, 256>>>(hidden);
    k_wprep<<<(HH*KTOT + 255)/256, 256>>>(conv_w);
    dim3 gg(256, 4);
    k_gemm<<<gg, 256, DSMEM>>>(hidden, conv_b, out_w);
    k_alpha<<<BT/256, 256>>>(mask, out_b);
    k_scan<<<16, 32>>>();
    dim3 go(TLEN, BB);
    k_out<<<go, 128>>>(hidden, out);
}